// round 12
// baseline (speedup 1.0000x reference)
#include <cuda_runtime.h>
#include <cuda_bf16.h>
#include <cstdint>

#define D_KEYC 128
#define BANKN  9720
#define NQ     1620
#define OBJN   3
#define M3     1536

// Scratch (device globals — no allocation allowed)
__device__ float g_P[(size_t)NQ * BANKN];              // fp32 logits
__device__ __nv_bfloat16 g_Ph[(size_t)NQ * BANKN];     // softmax probs, hi plane
__device__ __nv_bfloat16 g_Pl[(size_t)NQ * BANKN];     // softmax probs, lo plane
__device__ __nv_bfloat16 g_Vh[(size_t)M3 * BANKN];     // values, hi plane
__device__ __nv_bfloat16 g_Vl[(size_t)M3 * BANKN];     // values, lo plane
__device__ float g_mask[OBJN * NQ];                    // mask_mem[o][n]

// ============================================================================
// Common helpers
// ============================================================================
__device__ __forceinline__ uint32_t smem_u32(const void* p) {
    uint32_t a;
    asm("{ .reg .u64 t; cvta.to.shared.u64 t, %1; cvt.u32.u64 %0, t; }"
        : "=r"(a) : "l"(p));
    return a;
}

__device__ __forceinline__ void mma_bf16(float* d, const uint32_t* a, const uint32_t* b) {
    asm volatile(
        "mma.sync.aligned.m16n8k16.row.col.f32.bf16.bf16.f32 "
        "{%0,%1,%2,%3}, {%4,%5,%6,%7}, {%8,%9}, {%0,%1,%2,%3};"
        : "+f"(d[0]), "+f"(d[1]), "+f"(d[2]), "+f"(d[3])
        : "r"(a[0]), "r"(a[1]), "r"(a[2]), "r"(a[3]), "r"(b[0]), "r"(b[1]));
}

__device__ __forceinline__ void ldsm_x4(uint32_t* r, uint32_t addr) {
    asm volatile("ldmatrix.sync.aligned.m8n8.x4.shared.b16 {%0,%1,%2,%3}, [%4];"
                 : "=r"(r[0]), "=r"(r[1]), "=r"(r[2]), "=r"(r[3]) : "r"(addr));
}
__device__ __forceinline__ void ldsm_x4t(uint32_t* r, uint32_t addr) {
    asm volatile("ldmatrix.sync.aligned.m8n8.x4.trans.shared.b16 {%0,%1,%2,%3}, [%4];"
                 : "=r"(r[0]), "=r"(r[1]), "=r"(r[2]), "=r"(r[3]) : "r"(addr));
}
__device__ __forceinline__ void ldsm_x2(uint32_t* r, uint32_t addr) {
    asm volatile("ldmatrix.sync.aligned.m8n8.x2.shared.b16 {%0,%1}, [%2];"
                 : "=r"(r[0]), "=r"(r[1]) : "r"(addr));
}

// split fp32 -> bf16 hi + bf16 lo (lo = rn(v - hi)), packed as uint2 (4 lanes)
__device__ __forceinline__ void split_pack4(float4 v, uint2& h, uint2& l) {
    __nv_bfloat162 hxy = __floats2bfloat162_rn(v.x, v.y);
    __nv_bfloat162 hzw = __floats2bfloat162_rn(v.z, v.w);
    float2 hf0 = __bfloat1622float2(hxy);
    float2 hf1 = __bfloat1622float2(hzw);
    __nv_bfloat162 lxy = __floats2bfloat162_rn(v.x - hf0.x, v.y - hf0.y);
    __nv_bfloat162 lzw = __floats2bfloat162_rn(v.z - hf1.x, v.w - hf1.y);
    h.x = *(uint32_t*)&hxy; h.y = *(uint32_t*)&hzw;
    l.x = *(uint32_t*)&lxy; l.y = *(uint32_t*)&lzw;
}

// ============================================================================
// Kernel 1: S[n][k] = scale * sum_d q[d][n] * keys[d][k]  via bf16 mma x3.
// ============================================================================
#define DROW 136                         // halfs per d-row
#define QT_BYTES (128 * DROW * 2)        // 34816 per matrix
#define QAHI 0
#define QALO (QT_BYTES)
#define QBHI (2 * QT_BYTES)
#define QBLO (3 * QT_BYTES)
#define SMEM_QK (4 * QT_BYTES)           // 139264

__global__ __launch_bounds__(256, 1) void qk_mma(const float* __restrict__ keys,
                                                 const float* __restrict__ q) {
    extern __shared__ char smem[];
    const uint32_t sb = smem_u32(smem);
    const int tid = threadIdx.x;
    const int lane = tid & 31;
    const int wid = tid >> 5;
    const int g = lane >> 2, tg = lane & 3;
    const int wm = wid & 3;          // warp tile: 32 n
    const int wn = wid >> 2;         // warp tile: 64 k
    const int k0 = blockIdx.x * 128; // bank dim
    const int n0 = blockIdx.y * 128; // query dim
    const float scale = 0.08838834764831845f;

    #pragma unroll
    for (int it = 0; it < 16; it++) {
        int i = it * 256 + tid;
        int d = i >> 5, c4 = (i & 31) * 4;
        uint32_t dst = (uint32_t)(d * DROW + c4) * 2;

        float4 v = make_float4(0.f, 0.f, 0.f, 0.f);
        if (n0 + c4 < NQ) {
            v = *(const float4*)&q[(size_t)d * NQ + n0 + c4];
            v.x *= scale; v.y *= scale; v.z *= scale; v.w *= scale;
        }
        uint2 h, l; split_pack4(v, h, l);
        *(uint2*)(smem + QAHI + dst) = h;
        *(uint2*)(smem + QALO + dst) = l;

        float4 w = make_float4(0.f, 0.f, 0.f, 0.f);
        if (k0 + c4 < BANKN)
            w = *(const float4*)&keys[(size_t)d * BANKN + k0 + c4];
        split_pack4(w, h, l);
        *(uint2*)(smem + QBHI + dst) = h;
        *(uint2*)(smem + QBLO + dst) = l;
    }
    __syncthreads();

    float acc[2][8][4] = {};

    const int a_row_l = (lane & 7) + ((lane >> 4) << 3);
    const int a_col_l = ((lane >> 3) & 1) << 3;
    const int b_row_l = (lane & 7) + (((lane >> 3) & 1) << 3);
    const int b_col_l = (lane >> 4) << 3;

    #pragma unroll
    for (int ks = 0; ks < 8; ks++) {
        const int kk = ks * 16;
        uint32_t ah[2][4], al[2][4];
        #pragma unroll
        for (int mt = 0; mt < 2; mt++) {
            uint32_t off = (uint32_t)((kk + a_row_l) * DROW + wm * 32 + mt * 16 + a_col_l) * 2;
            ldsm_x4t(ah[mt], sb + QAHI + off);
            ldsm_x4t(al[mt], sb + QALO + off);
        }
        #pragma unroll
        for (int p = 0; p < 4; p++) {
            uint32_t off = (uint32_t)((kk + b_row_l) * DROW + wn * 64 + p * 16 + b_col_l) * 2;
            uint32_t bh[4], bl[4];
            ldsm_x4t(bh, sb + QBHI + off);
            ldsm_x4t(bl, sb + QBLO + off);
            #pragma unroll
            for (int mt = 0; mt < 2; mt++) {
                mma_bf16(acc[mt][2 * p],     ah[mt], bh);
                mma_bf16(acc[mt][2 * p],     ah[mt], bl);
                mma_bf16(acc[mt][2 * p],     al[mt], bh);
                mma_bf16(acc[mt][2 * p + 1], ah[mt], bh + 2);
                mma_bf16(acc[mt][2 * p + 1], ah[mt], bl + 2);
                mma_bf16(acc[mt][2 * p + 1], al[mt], bh + 2);
            }
        }
    }

    #pragma unroll
    for (int mt = 0; mt < 2; mt++) {
        int nt_ = n0 + wm * 32 + mt * 16 + g;
        int nb_ = nt_ + 8;
        #pragma unroll
        for (int nt = 0; nt < 8; nt++) {
            int k = k0 + wn * 64 + nt * 8 + tg * 2;
            if (k < BANKN) {
                if (nt_ < NQ)
                    *(float2*)&g_P[(size_t)nt_ * BANKN + k] =
                        make_float2(acc[mt][nt][0], acc[mt][nt][1]);
                if (nb_ < NQ)
                    *(float2*)&g_P[(size_t)nb_ * BANKN + k] =
                        make_float2(acc[mt][nt][2], acc[mt][nt][3]);
            }
        }
    }
}

// ============================================================================
// Kernel 2: row softmax of g_P -> bf16 hi/lo planes, + fused mask dots.
// ============================================================================
__global__ __launch_bounds__(256) void softmax_rows(const float* __restrict__ masks) {
    __shared__ float4 buf4[BANKN / 4];
    __shared__ float  sred[4][8];

    const int tid = threadIdx.x;
    const size_t rbase = (size_t)blockIdx.x * BANKN;
    const float4* r4 = (const float4*)(g_P + rbase);

    float mx = -3.0e38f;
    for (int i = tid; i < BANKN / 4; i += 256) {
        float4 v = r4[i];
        buf4[i] = v;
        mx = fmaxf(mx, fmaxf(fmaxf(v.x, v.y), fmaxf(v.z, v.w)));
    }
    #pragma unroll
    for (int o = 16; o; o >>= 1) mx = fmaxf(mx, __shfl_xor_sync(0xffffffffu, mx, o));
    if ((tid & 31) == 0) sred[0][tid >> 5] = mx;
    __syncthreads();
    mx = sred[0][0];
    #pragma unroll
    for (int w = 1; w < 8; w++) mx = fmaxf(mx, sred[0][w]);
    __syncthreads();

    float sum = 0.f, m0 = 0.f, m1 = 0.f, m2 = 0.f;
    const float4* mk0 = (const float4*)masks;
    const float4* mk1 = (const float4*)(masks + BANKN);
    const float4* mk2 = (const float4*)(masks + 2 * BANKN);
    for (int i = tid; i < BANKN / 4; i += 256) {
        float4 v = buf4[i];
        v.x = __expf(v.x - mx); v.y = __expf(v.y - mx);
        v.z = __expf(v.z - mx); v.w = __expf(v.w - mx);
        buf4[i] = v;
        sum += (v.x + v.y) + (v.z + v.w);
        float4 a = mk0[i], b = mk1[i], c = mk2[i];
        m0 += a.x * v.x + a.y * v.y + a.z * v.z + a.w * v.w;
        m1 += b.x * v.x + b.y * v.y + b.z * v.z + b.w * v.w;
        m2 += c.x * v.x + c.y * v.y + c.z * v.z + c.w * v.w;
    }
    float vals[4] = {sum, m0, m1, m2};
    #pragma unroll
    for (int r = 0; r < 4; r++) {
        float v = vals[r];
        #pragma unroll
        for (int o = 16; o; o >>= 1) v += __shfl_xor_sync(0xffffffffu, v, o);
        if ((tid & 31) == 0) sred[r][tid >> 5] = v;
    }
    __syncthreads();
    float tot = 0.f;
    #pragma unroll
    for (int w = 0; w < 8; w++) tot += sred[0][w];
    const float inv = 1.f / tot;

    if (tid < 3) {
        float t = 0.f;
        #pragma unroll
        for (int w = 0; w < 8; w++) t += sred[tid + 1][w];
        g_mask[tid * NQ + blockIdx.x] = t * inv;
    }

    for (int i = tid; i < BANKN / 4; i += 256) {
        float4 v = buf4[i];
        v.x *= inv; v.y *= inv; v.z *= inv; v.w *= inv;
        uint2 h, l; split_pack4(v, h, l);
        *(uint2*)&g_Ph[rbase + (size_t)i * 4] = h;
        *(uint2*)&g_Pl[rbase + (size_t)i * 4] = l;
    }
}

// ============================================================================
// Kernel 2b: pre-split V into bf16 hi/lo planes (one pass)
// ============================================================================
__global__ __launch_bounds__(256) void conv_v(const float* __restrict__ V) {
    size_t i = (size_t)blockIdx.x * 256 + threadIdx.x;
    const size_t total4 = (size_t)M3 * BANKN / 4;
    if (i >= total4) return;
    float4 v = *(const float4*)&V[i * 4];
    uint2 h, l; split_pack4(v, h, l);
    *(uint2*)&g_Vh[i * 4] = h;
    *(uint2*)&g_Vl[i * 4] = l;
}

// ============================================================================
// Kernel 3: mem[r][n] = sum_k V[r][k] * P[n][k], bf16 mma x3 + ldmatrix.
// Chunk body rescheduled: ks0 LDSM -> LDG(c+1) -> ks0 MMAs -> STS(c+1) ->
// ks1 LDSM -> ks1 MMAs -> bar. The ks1 MMA block (~750 cyc) hides the STS
// drain so the barrier arrives with stores retired (BAR drains pending STS).
// Block 128m x 144n, K-chunk 32, grid 12x12 (one wave), double buffered.
// ============================================================================
#define KC 304
#define ROWP 40                    // smem row stride in halfs
#define OFF_AHI 0
#define OFF_ALO 10240
#define OFF_BHI 20480
#define OFF_BLO 32000
#define BUF_BYTES 43520
#define SMEM_VAL (2 * BUF_BYTES)   // 87040

struct StageV {
    uint4 ah[2], al[2], bh[3], bl[3];
};

__device__ __forceinline__ void ldg_chunk(int m0, int n0, int k0, int tid, StageV& s) {
    const uint4 z = make_uint4(0, 0, 0, 0);
    #pragma unroll
    for (int it = 0; it < 2; it++) {
        int i = it * 256 + tid;
        int m = i >> 2, kc = (i & 3) * 8;
        if (k0 + kc < BANKN) {
            size_t off = (size_t)(m0 + m) * BANKN + k0 + kc;
            s.ah[it] = *(const uint4*)&g_Vh[off];
            s.al[it] = *(const uint4*)&g_Vl[off];
        } else { s.ah[it] = z; s.al[it] = z; }
    }
    #pragma unroll
    for (int it = 0; it < 3; it++) {
        int i = it * 256 + tid;
        s.bh[it] = z; s.bl[it] = z;
        if (i < 576) {
            int r = i >> 2, kc = (i & 3) * 8;
            if (n0 + r < NQ && k0 + kc < BANKN) {
                size_t off = (size_t)(n0 + r) * BANKN + k0 + kc;
                s.bh[it] = *(const uint4*)&g_Ph[off];
                s.bl[it] = *(const uint4*)&g_Pl[off];
            }
        }
    }
}

__device__ __forceinline__ void sts_chunk(char* buf, int tid, const StageV& s) {
    #pragma unroll
    for (int it = 0; it < 2; it++) {
        int i = it * 256 + tid;
        int m = i >> 2, kc = (i & 3) * 8;
        *(uint4*)(buf + OFF_AHI + (m * ROWP + kc) * 2) = s.ah[it];
        *(uint4*)(buf + OFF_ALO + (m * ROWP + kc) * 2) = s.al[it];
    }
    #pragma unroll
    for (int it = 0; it < 3; it++) {
        int i = it * 256 + tid;
        if (i < 576) {
            int r = i >> 2, kc = (i & 3) * 8;
            *(uint4*)(buf + OFF_BHI + (r * ROWP + kc) * 2) = s.bh[it];
            *(uint4*)(buf + OFF_BLO + (r * ROWP + kc) * 2) = s.bl[it];
        }
    }
}

struct FragKS {
    uint32_t ah[2][4], al[2][4], bh[4][4], bl[4][4], b2h[2], b2l[2];
};

__device__ __forceinline__ void ldsm_ks(FragKS& f, uint32_t base, int kk,
                                        int wm, int wn,
                                        int av_row, int av_col,
                                        int bv_row, int bv_col,
                                        int b2_row, int b2_col) {
    #pragma unroll
    for (int mt = 0; mt < 2; mt++) {
        uint32_t off = (uint32_t)((wm * 32 + mt * 16 + av_row) * ROWP + kk + av_col) * 2;
        ldsm_x4(f.ah[mt], base + OFF_AHI + off);
        ldsm_x4(f.al[mt], base + OFF_ALO + off);
    }
    #pragma unroll
    for (int p = 0; p < 4; p++) {
        uint32_t off = (uint32_t)((wn * 72 + p * 16 + bv_row) * ROWP + kk + bv_col) * 2;
        ldsm_x4(f.bh[p], base + OFF_BHI + off);
        ldsm_x4(f.bl[p], base + OFF_BLO + off);
    }
    {
        uint32_t off = (uint32_t)((wn * 72 + 64 + b2_row) * ROWP + kk + b2_col) * 2;
        ldsm_x2(f.b2h, base + OFF_BHI + off);
        ldsm_x2(f.b2l, base + OFF_BLO + off);
    }
}

__device__ __forceinline__ void mma_ks(float acc[2][9][4], const FragKS& f) {
    #pragma unroll
    for (int p = 0; p < 4; p++)
        #pragma unroll
        for (int mt = 0; mt < 2; mt++) {
            mma_bf16(acc[mt][2 * p],     f.ah[mt], f.bh[p]);
            mma_bf16(acc[mt][2 * p],     f.ah[mt], f.bl[p]);
            mma_bf16(acc[mt][2 * p],     f.al[mt], f.bh[p]);
            mma_bf16(acc[mt][2 * p + 1], f.ah[mt], f.bh[p] + 2);
            mma_bf16(acc[mt][2 * p + 1], f.ah[mt], f.bl[p] + 2);
            mma_bf16(acc[mt][2 * p + 1], f.al[mt], f.bh[p] + 2);
        }
    #pragma unroll
    for (int mt = 0; mt < 2; mt++) {
        mma_bf16(acc[mt][8], f.ah[mt], f.b2h);
        mma_bf16(acc[mt][8], f.ah[mt], f.b2l);
        mma_bf16(acc[mt][8], f.al[mt], f.b2h);
    }
}

__global__ __launch_bounds__(256, 1) void val_gemm_mma(float* __restrict__ out) {
    extern __shared__ char smem[];
    const uint32_t sb = smem_u32(smem);
    const int tid = threadIdx.x;
    const int wid = tid >> 5;
    const int lane = tid & 31;
    const int g = lane >> 2, tg = lane & 3;
    const int wm = wid & 3;
    const int wn = wid >> 2;
    const int n0 = blockIdx.x * 144;
    const int m0 = blockIdx.y * 128;

    const int av_row = (lane & 7) + (((lane >> 3) & 1) << 3);
    const int av_col = (lane >> 4) << 3;
    const int bv_row = (lane & 7) + ((lane >> 4) << 3);
    const int bv_col = ((lane >> 3) & 1) << 3;
    const int b2_row = lane & 7;
    const int b2_col = ((lane >> 3) & 1) << 3;

    float acc[2][9][4] = {};

    {
        StageV s;
        ldg_chunk(m0, n0, 0, tid, s);
        sts_chunk(smem, tid, s);
    }
    __syncthreads();

    for (int c = 0; c < KC; c++) {
        const uint32_t base = sb + (uint32_t)(c & 1) * BUF_BYTES;
        char* nbuf = smem + (size_t)((c + 1) & 1) * BUF_BYTES;
        const bool more = (c + 1 < KC);

        FragKS f;
        // ks0 fragments first so MMAs can start immediately
        ldsm_ks(f, base, 0, wm, wn, av_row, av_col, bv_row, bv_col, b2_row, b2_col);

        // issue next chunk's global loads; latency covered by ks0 MMA block
        StageV s;
        if (more) ldg_chunk(m0, n0, (c + 1) * 32, tid, s);

        mma_ks(acc, f);

        // store next chunk mid-body: ks1 MMA block below hides the STS drain
        if (more) sts_chunk(nbuf, tid, s);

        ldsm_ks(f, base, 16, wm, wn, av_row, av_col, bv_row, bv_col, b2_row, b2_col);
        mma_ks(acc, f);

        __syncthreads();
    }

    const int n_base = n0 + wn * 72;
    const int m_base = m0 + wm * 32;
    #pragma unroll
    for (int mt = 0; mt < 2; mt++) {
        int rt = m_base + mt * 16 + g;
        int rb = rt + 8;
        float* row_t = out + (size_t)((rt >> 9) * 1024 + (rt & 511)) * NQ;
        float* row_b = out + (size_t)((rb >> 9) * 1024 + (rb & 511)) * NQ;
        #pragma unroll
        for (int nt = 0; nt < 9; nt++) {
            int n = n_base + nt * 8 + tg * 2;
            if (n < NQ) {
                *(float2*)&row_t[n] = make_float2(acc[mt][nt][0], acc[mt][nt][1]);
                *(float2*)&row_b[n] = make_float2(acc[mt][nt][2], acc[mt][nt][3]);
            }
        }
    }
}

// ============================================================================
// Kernel 4: out[o][512+c][n] = q_out[o][c][n] * mask_mem[o][n]
// ============================================================================
__global__ __launch_bounds__(256) void apply_mask(const float* __restrict__ q_out,
                                                  float* __restrict__ out) {
    int idx = blockIdx.x * 256 + threadIdx.x;
    const int total = OBJN * 512 * NQ;
    if (idx >= total) return;
    int n    = idx % NQ;
    int rest = idx / NQ;
    int c    = rest % 512;
    int o    = rest / 512;
    out[(size_t)(o * 1024 + 512 + c) * NQ + n] = q_out[idx] * g_mask[o * NQ + n];
}

// ============================================================================
extern "C" void kernel_launch(void* const* d_in, const int* in_sizes, int n_in,
                              void* d_out, int out_size) {
    const float* keys   = (const float*)d_in[0];  // (128, 9720)
    const float* q_in   = (const float*)d_in[1];  // (1, 128, 1620)
    const float* q_out  = (const float*)d_in[2];  // (3, 512, 1620)
    const float* values = (const float*)d_in[3];  // (3, 512, 9720)
    const float* masks  = (const float*)d_in[4];  // (3, 1, 9720)
    float* out = (float*)d_out;                   // (1, 3, 1024, 1620)

    (void)in_sizes; (void)n_in; (void)out_size;

    cudaFuncSetAttribute(qk_mma, cudaFuncAttributeMaxDynamicSharedMemorySize, SMEM_QK);
    cudaFuncSetAttribute(val_gemm_mma, cudaFuncAttributeMaxDynamicSharedMemorySize, SMEM_VAL);

    dim3 g1((BANKN + 127) / 128, (NQ + 127) / 128);   // 76 x 13
    qk_mma<<<g1, 256, SMEM_QK>>>(keys, q_in);         // launch 0

    softmax_rows<<<NQ, 256>>>(masks);                 // launch 1

    const int convN = (int)(((size_t)M3 * BANKN / 4 + 255) / 256);
    conv_v<<<convN, 256>>>(values);                   // launch 2 (independent)

    dim3 g3(12, 12);
    val_gemm_mma<<<g3, 256, SMEM_VAL>>>(out);         // launch 3 (profiled slot)

    apply_mask<<<(OBJN * 512 * NQ + 255) / 256, 256>>>(q_out, out);  // launch 4
}

// round 13
// speedup vs baseline: 1.1195x; 1.1195x over previous
#include <cuda_runtime.h>
#include <cuda_bf16.h>
#include <cstdint>

#define D_KEYC 128
#define BANKN  9720
#define NQ     1620
#define OBJN   3
#define M3     1536

// Scratch (device globals — no allocation allowed)
__device__ float g_P[(size_t)NQ * BANKN];              // fp32 logits
__device__ __nv_bfloat16 g_Ph[(size_t)NQ * BANKN];     // softmax probs, hi plane
__device__ __nv_bfloat16 g_Pl[(size_t)NQ * BANKN];     // softmax probs, lo plane
__device__ __nv_bfloat16 g_Vh[(size_t)M3 * BANKN];     // values, hi plane
__device__ __nv_bfloat16 g_Vl[(size_t)M3 * BANKN];     // values, lo plane
__device__ float g_mask[OBJN * NQ];                    // mask_mem[o][n]

// ============================================================================
// Common helpers
// ============================================================================
__device__ __forceinline__ uint32_t smem_u32(const void* p) {
    uint32_t a;
    asm("{ .reg .u64 t; cvta.to.shared.u64 t, %1; cvt.u32.u64 %0, t; }"
        : "=r"(a) : "l"(p));
    return a;
}

__device__ __forceinline__ void mma_bf16(float* d, const uint32_t* a, const uint32_t* b) {
    asm volatile(
        "mma.sync.aligned.m16n8k16.row.col.f32.bf16.bf16.f32 "
        "{%0,%1,%2,%3}, {%4,%5,%6,%7}, {%8,%9}, {%0,%1,%2,%3};"
        : "+f"(d[0]), "+f"(d[1]), "+f"(d[2]), "+f"(d[3])
        : "r"(a[0]), "r"(a[1]), "r"(a[2]), "r"(a[3]), "r"(b[0]), "r"(b[1]));
}

__device__ __forceinline__ void ldsm_x4(uint32_t* r, uint32_t addr) {
    asm volatile("ldmatrix.sync.aligned.m8n8.x4.shared.b16 {%0,%1,%2,%3}, [%4];"
                 : "=r"(r[0]), "=r"(r[1]), "=r"(r[2]), "=r"(r[3]) : "r"(addr));
}
__device__ __forceinline__ void ldsm_x4t(uint32_t* r, uint32_t addr) {
    asm volatile("ldmatrix.sync.aligned.m8n8.x4.trans.shared.b16 {%0,%1,%2,%3}, [%4];"
                 : "=r"(r[0]), "=r"(r[1]), "=r"(r[2]), "=r"(r[3]) : "r"(addr));
}

// split fp32 -> bf16 hi + bf16 lo (lo = rn(v - hi)), packed as uint2 (4 lanes)
__device__ __forceinline__ void split_pack4(float4 v, uint2& h, uint2& l) {
    __nv_bfloat162 hxy = __floats2bfloat162_rn(v.x, v.y);
    __nv_bfloat162 hzw = __floats2bfloat162_rn(v.z, v.w);
    float2 hf0 = __bfloat1622float2(hxy);
    float2 hf1 = __bfloat1622float2(hzw);
    __nv_bfloat162 lxy = __floats2bfloat162_rn(v.x - hf0.x, v.y - hf0.y);
    __nv_bfloat162 lzw = __floats2bfloat162_rn(v.z - hf1.x, v.w - hf1.y);
    h.x = *(uint32_t*)&hxy; h.y = *(uint32_t*)&hzw;
    l.x = *(uint32_t*)&lxy; l.y = *(uint32_t*)&lzw;
}

// ============================================================================
// Kernel 1: S[n][k] = scale * sum_d q[d][n] * keys[d][k]  via bf16 mma x3.
// ============================================================================
#define DROW 136                         // halfs per d-row
#define QT_BYTES (128 * DROW * 2)        // 34816 per matrix
#define QAHI 0
#define QALO (QT_BYTES)
#define QBHI (2 * QT_BYTES)
#define QBLO (3 * QT_BYTES)
#define SMEM_QK (4 * QT_BYTES)           // 139264

__global__ __launch_bounds__(256, 1) void qk_mma(const float* __restrict__ keys,
                                                 const float* __restrict__ q) {
    extern __shared__ char smem[];
    const uint32_t sb = smem_u32(smem);
    const int tid = threadIdx.x;
    const int lane = tid & 31;
    const int wid = tid >> 5;
    const int g = lane >> 2, tg = lane & 3;
    const int wm = wid & 3;          // warp tile: 32 n
    const int wn = wid >> 2;         // warp tile: 64 k
    const int k0 = blockIdx.x * 128; // bank dim
    const int n0 = blockIdx.y * 128; // query dim
    const float scale = 0.08838834764831845f;

    #pragma unroll
    for (int it = 0; it < 16; it++) {
        int i = it * 256 + tid;
        int d = i >> 5, c4 = (i & 31) * 4;
        uint32_t dst = (uint32_t)(d * DROW + c4) * 2;

        float4 v = make_float4(0.f, 0.f, 0.f, 0.f);
        if (n0 + c4 < NQ) {
            v = *(const float4*)&q[(size_t)d * NQ + n0 + c4];
            v.x *= scale; v.y *= scale; v.z *= scale; v.w *= scale;
        }
        uint2 h, l; split_pack4(v, h, l);
        *(uint2*)(smem + QAHI + dst) = h;
        *(uint2*)(smem + QALO + dst) = l;

        float4 w = make_float4(0.f, 0.f, 0.f, 0.f);
        if (k0 + c4 < BANKN)
            w = *(const float4*)&keys[(size_t)d * BANKN + k0 + c4];
        split_pack4(w, h, l);
        *(uint2*)(smem + QBHI + dst) = h;
        *(uint2*)(smem + QBLO + dst) = l;
    }
    __syncthreads();

    float acc[2][8][4] = {};

    const int a_row_l = (lane & 7) + ((lane >> 4) << 3);
    const int a_col_l = ((lane >> 3) & 1) << 3;
    const int b_row_l = (lane & 7) + (((lane >> 3) & 1) << 3);
    const int b_col_l = (lane >> 4) << 3;

    #pragma unroll
    for (int ks = 0; ks < 8; ks++) {
        const int kk = ks * 16;
        uint32_t ah[2][4], al[2][4];
        #pragma unroll
        for (int mt = 0; mt < 2; mt++) {
            uint32_t off = (uint32_t)((kk + a_row_l) * DROW + wm * 32 + mt * 16 + a_col_l) * 2;
            ldsm_x4t(ah[mt], sb + QAHI + off);
            ldsm_x4t(al[mt], sb + QALO + off);
        }
        #pragma unroll
        for (int p = 0; p < 4; p++) {
            uint32_t off = (uint32_t)((kk + b_row_l) * DROW + wn * 64 + p * 16 + b_col_l) * 2;
            uint32_t bh[4], bl[4];
            ldsm_x4t(bh, sb + QBHI + off);
            ldsm_x4t(bl, sb + QBLO + off);
            #pragma unroll
            for (int mt = 0; mt < 2; mt++) {
                mma_bf16(acc[mt][2 * p],     ah[mt], bh);
                mma_bf16(acc[mt][2 * p],     ah[mt], bl);
                mma_bf16(acc[mt][2 * p],     al[mt], bh);
                mma_bf16(acc[mt][2 * p + 1], ah[mt], bh + 2);
                mma_bf16(acc[mt][2 * p + 1], ah[mt], bl + 2);
                mma_bf16(acc[mt][2 * p + 1], al[mt], bh + 2);
            }
        }
    }

    #pragma unroll
    for (int mt = 0; mt < 2; mt++) {
        int nt_ = n0 + wm * 32 + mt * 16 + g;
        int nb_ = nt_ + 8;
        #pragma unroll
        for (int nt = 0; nt < 8; nt++) {
            int k = k0 + wn * 64 + nt * 8 + tg * 2;
            if (k < BANKN) {
                if (nt_ < NQ)
                    *(float2*)&g_P[(size_t)nt_ * BANKN + k] =
                        make_float2(acc[mt][nt][0], acc[mt][nt][1]);
                if (nb_ < NQ)
                    *(float2*)&g_P[(size_t)nb_ * BANKN + k] =
                        make_float2(acc[mt][nt][2], acc[mt][nt][3]);
            }
        }
    }
}

// ============================================================================
// Kernel 2: row softmax of g_P -> bf16 hi/lo planes, + fused mask dots.
// ============================================================================
__global__ __launch_bounds__(256) void softmax_rows(const float* __restrict__ masks) {
    __shared__ float4 buf4[BANKN / 4];
    __shared__ float  sred[4][8];

    const int tid = threadIdx.x;
    const size_t rbase = (size_t)blockIdx.x * BANKN;
    const float4* r4 = (const float4*)(g_P + rbase);

    float mx = -3.0e38f;
    for (int i = tid; i < BANKN / 4; i += 256) {
        float4 v = r4[i];
        buf4[i] = v;
        mx = fmaxf(mx, fmaxf(fmaxf(v.x, v.y), fmaxf(v.z, v.w)));
    }
    #pragma unroll
    for (int o = 16; o; o >>= 1) mx = fmaxf(mx, __shfl_xor_sync(0xffffffffu, mx, o));
    if ((tid & 31) == 0) sred[0][tid >> 5] = mx;
    __syncthreads();
    mx = sred[0][0];
    #pragma unroll
    for (int w = 1; w < 8; w++) mx = fmaxf(mx, sred[0][w]);
    __syncthreads();

    float sum = 0.f, m0 = 0.f, m1 = 0.f, m2 = 0.f;
    const float4* mk0 = (const float4*)masks;
    const float4* mk1 = (const float4*)(masks + BANKN);
    const float4* mk2 = (const float4*)(masks + 2 * BANKN);
    for (int i = tid; i < BANKN / 4; i += 256) {
        float4 v = buf4[i];
        v.x = __expf(v.x - mx); v.y = __expf(v.y - mx);
        v.z = __expf(v.z - mx); v.w = __expf(v.w - mx);
        buf4[i] = v;
        sum += (v.x + v.y) + (v.z + v.w);
        float4 a = mk0[i], b = mk1[i], c = mk2[i];
        m0 += a.x * v.x + a.y * v.y + a.z * v.z + a.w * v.w;
        m1 += b.x * v.x + b.y * v.y + b.z * v.z + b.w * v.w;
        m2 += c.x * v.x + c.y * v.y + c.z * v.z + c.w * v.w;
    }
    float vals[4] = {sum, m0, m1, m2};
    #pragma unroll
    for (int r = 0; r < 4; r++) {
        float v = vals[r];
        #pragma unroll
        for (int o = 16; o; o >>= 1) v += __shfl_xor_sync(0xffffffffu, v, o);
        if ((tid & 31) == 0) sred[r][tid >> 5] = v;
    }
    __syncthreads();
    float tot = 0.f;
    #pragma unroll
    for (int w = 0; w < 8; w++) tot += sred[0][w];
    const float inv = 1.f / tot;

    if (tid < 3) {
        float t = 0.f;
        #pragma unroll
        for (int w = 0; w < 8; w++) t += sred[tid + 1][w];
        g_mask[tid * NQ + blockIdx.x] = t * inv;
    }

    for (int i = tid; i < BANKN / 4; i += 256) {
        float4 v = buf4[i];
        v.x *= inv; v.y *= inv; v.z *= inv; v.w *= inv;
        uint2 h, l; split_pack4(v, h, l);
        *(uint2*)&g_Ph[rbase + (size_t)i * 4] = h;
        *(uint2*)&g_Pl[rbase + (size_t)i * 4] = l;
    }
}

// ============================================================================
// Kernel 2b: pre-split V into bf16 hi/lo planes (one pass)
// ============================================================================
__global__ __launch_bounds__(256) void conv_v(const float* __restrict__ V) {
    size_t i = (size_t)blockIdx.x * 256 + threadIdx.x;
    const size_t total4 = (size_t)M3 * BANKN / 4;
    if (i >= total4) return;
    float4 v = *(const float4*)&V[i * 4];
    uint2 h, l; split_pack4(v, h, l);
    *(uint2*)&g_Vh[i * 4] = h;
    *(uint2*)&g_Vl[i * 4] = l;
}

// ============================================================================
// Kernel 3: mem[r][n] = sum_k V[r][k] * P[n][k], bf16 mma x3 + ldmatrix.
// R9 loop order (measured best). Wider warp n-tile to cut LDSM-per-MMA:
// CTA 128m x 160n, warps 4m x 2n -> warp tile 32m x 80n (5 clean x4 B pairs).
// Per warp per ks: 60 MMA vs 14 LDSM (was 54:22). Grid 11x12 = 132 CTAs.
// ============================================================================
#define KC 304
#define NTILE 160
#define ROWP 40                    // smem row stride in halfs
#define OFF_AHI 0
#define OFF_ALO 10240              // 128*40*2
#define OFF_BHI 20480
#define OFF_BLO 33280              // 20480 + 160*40*2
#define BUF_BYTES 46080            // 33280 + 12800
#define SMEM_VAL (2 * BUF_BYTES)   // 92160

struct StageV {
    uint4 ah[2], al[2], bh[3], bl[3];
};

__device__ __forceinline__ void ldg_chunk(int m0, int n0, int k0, int tid, StageV& s) {
    const uint4 z = make_uint4(0, 0, 0, 0);
    #pragma unroll
    for (int it = 0; it < 2; it++) {
        int i = it * 256 + tid;
        int m = i >> 2, kc = (i & 3) * 8;
        if (k0 + kc < BANKN) {
            size_t off = (size_t)(m0 + m) * BANKN + k0 + kc;
            s.ah[it] = *(const uint4*)&g_Vh[off];
            s.al[it] = *(const uint4*)&g_Vl[off];
        } else { s.ah[it] = z; s.al[it] = z; }
    }
    #pragma unroll
    for (int it = 0; it < 3; it++) {
        int i = it * 256 + tid;
        s.bh[it] = z; s.bl[it] = z;
        if (i < 640) {               // 160 rows * 4 uint4
            int r = i >> 2, kc = (i & 3) * 8;
            if (n0 + r < NQ && k0 + kc < BANKN) {
                size_t off = (size_t)(n0 + r) * BANKN + k0 + kc;
                s.bh[it] = *(const uint4*)&g_Ph[off];
                s.bl[it] = *(const uint4*)&g_Pl[off];
            }
        }
    }
}

__device__ __forceinline__ void sts_chunk(char* buf, int tid, const StageV& s) {
    #pragma unroll
    for (int it = 0; it < 2; it++) {
        int i = it * 256 + tid;
        int m = i >> 2, kc = (i & 3) * 8;
        *(uint4*)(buf + OFF_AHI + (m * ROWP + kc) * 2) = s.ah[it];
        *(uint4*)(buf + OFF_ALO + (m * ROWP + kc) * 2) = s.al[it];
    }
    #pragma unroll
    for (int it = 0; it < 3; it++) {
        int i = it * 256 + tid;
        if (i < 640) {
            int r = i >> 2, kc = (i & 3) * 8;
            *(uint4*)(buf + OFF_BHI + (r * ROWP + kc) * 2) = s.bh[it];
            *(uint4*)(buf + OFF_BLO + (r * ROWP + kc) * 2) = s.bl[it];
        }
    }
}

__global__ __launch_bounds__(256, 1) void val_gemm_mma(float* __restrict__ out) {
    extern __shared__ char smem[];
    const uint32_t sb = smem_u32(smem);
    const int tid = threadIdx.x;
    const int wid = tid >> 5;
    const int lane = tid & 31;
    const int g = lane >> 2, tg = lane & 3;
    const int wm = wid & 3;            // 4 warps over m (32 each)
    const int wn = wid >> 2;           // 2 warps over n (80 each)
    const int n0 = blockIdx.x * NTILE;
    const int m0 = blockIdx.y * 128;

    const int av_row = (lane & 7) + (((lane >> 3) & 1) << 3);
    const int av_col = (lane >> 4) << 3;
    const int bv_row = (lane & 7) + ((lane >> 4) << 3);
    const int bv_col = ((lane >> 3) & 1) << 3;

    float acc[2][10][4] = {};

    {
        StageV s;
        ldg_chunk(m0, n0, 0, tid, s);
        sts_chunk(smem, tid, s);
    }
    __syncthreads();

    for (int c = 0; c < KC; c++) {
        const uint32_t boff = (uint32_t)(c & 1) * BUF_BYTES;
        char* nbuf = smem + (size_t)((c + 1) & 1) * BUF_BYTES;

        StageV s;
        const bool more = (c + 1 < KC);
        if (more) ldg_chunk(m0, n0, (c + 1) * 32, tid, s);

        #pragma unroll
        for (int ks = 0; ks < 2; ks++) {
            const int kk = ks * 16;
            uint32_t ah[2][4], al[2][4];
            #pragma unroll
            for (int mt = 0; mt < 2; mt++) {
                uint32_t off = (uint32_t)((wm * 32 + mt * 16 + av_row) * ROWP + kk + av_col) * 2;
                ldsm_x4(ah[mt], sb + boff + OFF_AHI + off);
                ldsm_x4(al[mt], sb + boff + OFF_ALO + off);
            }
            #pragma unroll
            for (int p = 0; p < 5; p++) {
                uint32_t off = (uint32_t)((wn * 80 + p * 16 + bv_row) * ROWP + kk + bv_col) * 2;
                uint32_t bh[4], bl[4];
                ldsm_x4(bh, sb + boff + OFF_BHI + off);
                ldsm_x4(bl, sb + boff + OFF_BLO + off);
                #pragma unroll
                for (int mt = 0; mt < 2; mt++) {
                    mma_bf16(acc[mt][2 * p],     ah[mt], bh);
                    mma_bf16(acc[mt][2 * p],     ah[mt], bl);
                    mma_bf16(acc[mt][2 * p],     al[mt], bh);
                    mma_bf16(acc[mt][2 * p + 1], ah[mt], bh + 2);
                    mma_bf16(acc[mt][2 * p + 1], ah[mt], bl + 2);
                    mma_bf16(acc[mt][2 * p + 1], al[mt], bh + 2);
                }
            }
        }

        if (more) sts_chunk(nbuf, tid, s);
        __syncthreads();
    }

    const int n_base = n0 + wn * 80;
    const int m_base = m0 + wm * 32;
    #pragma unroll
    for (int mt = 0; mt < 2; mt++) {
        int rt = m_base + mt * 16 + g;
        int rb = rt + 8;
        float* row_t = out + (size_t)((rt >> 9) * 1024 + (rt & 511)) * NQ;
        float* row_b = out + (size_t)((rb >> 9) * 1024 + (rb & 511)) * NQ;
        #pragma unroll
        for (int nt = 0; nt < 10; nt++) {
            int n = n_base + nt * 8 + tg * 2;
            if (n < NQ) {
                *(float2*)&row_t[n] = make_float2(acc[mt][nt][0], acc[mt][nt][1]);
                *(float2*)&row_b[n] = make_float2(acc[mt][nt][2], acc[mt][nt][3]);
            }
        }
    }
}

// ============================================================================
// Kernel 4: out[o][512+c][n] = q_out[o][c][n] * mask_mem[o][n]
// ============================================================================
__global__ __launch_bounds__(256) void apply_mask(const float* __restrict__ q_out,
                                                  float* __restrict__ out) {
    int idx = blockIdx.x * 256 + threadIdx.x;
    const int total = OBJN * 512 * NQ;
    if (idx >= total) return;
    int n    = idx % NQ;
    int rest = idx / NQ;
    int c    = rest % 512;
    int o    = rest / 512;
    out[(size_t)(o * 1024 + 512 + c) * NQ + n] = q_out[idx] * g_mask[o * NQ + n];
}

// ============================================================================
extern "C" void kernel_launch(void* const* d_in, const int* in_sizes, int n_in,
                              void* d_out, int out_size) {
    const float* keys   = (const float*)d_in[0];  // (128, 9720)
    const float* q_in   = (const float*)d_in[1];  // (1, 128, 1620)
    const float* q_out  = (const float*)d_in[2];  // (3, 512, 1620)
    const float* values = (const float*)d_in[3];  // (3, 512, 9720)
    const float* masks  = (const float*)d_in[4];  // (3, 1, 9720)
    float* out = (float*)d_out;                   // (1, 3, 1024, 1620)

    (void)in_sizes; (void)n_in; (void)out_size;

    cudaFuncSetAttribute(qk_mma, cudaFuncAttributeMaxDynamicSharedMemorySize, SMEM_QK);
    cudaFuncSetAttribute(val_gemm_mma, cudaFuncAttributeMaxDynamicSharedMemorySize, SMEM_VAL);

    dim3 g1((BANKN + 127) / 128, (NQ + 127) / 128);   // 76 x 13
    qk_mma<<<g1, 256, SMEM_QK>>>(keys, q_in);         // launch 0

    softmax_rows<<<NQ, 256>>>(masks);                 // launch 1

    const int convN = (int)(((size_t)M3 * BANKN / 4 + 255) / 256);
    conv_v<<<convN, 256>>>(values);                   // launch 2 (independent)

    dim3 g3((NQ + NTILE - 1) / NTILE, 12);            // 11 x 12 = 132 CTAs
    val_gemm_mma<<<g3, 256, SMEM_VAL>>>(out);         // launch 3 (profiled slot)

    apply_mask<<<(OBJN * 512 * NQ + 255) / 256, 256>>>(q_out, out);  // launch 4
}

// round 14
// speedup vs baseline: 1.1807x; 1.0547x over previous
#include <cuda_runtime.h>
#include <cuda_bf16.h>
#include <cstdint>

#define D_KEYC 128
#define BANKN  9720
#define NQ     1620
#define OBJN   3
#define M3     1536

// Scratch (device globals — no allocation allowed)
__device__ float g_P[(size_t)NQ * BANKN];              // fp32 logits
__device__ __nv_bfloat16 g_Ph[(size_t)NQ * BANKN];     // softmax probs, hi plane
__device__ __nv_bfloat16 g_Pl[(size_t)NQ * BANKN];     // softmax probs, lo plane
__device__ __nv_bfloat16 g_Vh[(size_t)M3 * BANKN];     // values, hi plane
__device__ __nv_bfloat16 g_Vl[(size_t)M3 * BANKN];     // values, lo plane
__device__ float g_mask[OBJN * NQ];                    // mask_mem[o][n]

// ============================================================================
// Common helpers
// ============================================================================
__device__ __forceinline__ uint32_t smem_u32(const void* p) {
    uint32_t a;
    asm("{ .reg .u64 t; cvta.to.shared.u64 t, %1; cvt.u32.u64 %0, t; }"
        : "=r"(a) : "l"(p));
    return a;
}

__device__ __forceinline__ void mma_bf16(float* d, const uint32_t* a, const uint32_t* b) {
    asm volatile(
        "mma.sync.aligned.m16n8k16.row.col.f32.bf16.bf16.f32 "
        "{%0,%1,%2,%3}, {%4,%5,%6,%7}, {%8,%9}, {%0,%1,%2,%3};"
        : "+f"(d[0]), "+f"(d[1]), "+f"(d[2]), "+f"(d[3])
        : "r"(a[0]), "r"(a[1]), "r"(a[2]), "r"(a[3]), "r"(b[0]), "r"(b[1]));
}

__device__ __forceinline__ void ldsm_x4(uint32_t* r, uint32_t addr) {
    asm volatile("ldmatrix.sync.aligned.m8n8.x4.shared.b16 {%0,%1,%2,%3}, [%4];"
                 : "=r"(r[0]), "=r"(r[1]), "=r"(r[2]), "=r"(r[3]) : "r"(addr));
}
__device__ __forceinline__ void ldsm_x4t(uint32_t* r, uint32_t addr) {
    asm volatile("ldmatrix.sync.aligned.m8n8.x4.trans.shared.b16 {%0,%1,%2,%3}, [%4];"
                 : "=r"(r[0]), "=r"(r[1]), "=r"(r[2]), "=r"(r[3]) : "r"(addr));
}

// split fp32 -> bf16 hi + bf16 lo (lo = rn(v - hi)), packed as uint2 (4 lanes)
__device__ __forceinline__ void split_pack4(float4 v, uint2& h, uint2& l) {
    __nv_bfloat162 hxy = __floats2bfloat162_rn(v.x, v.y);
    __nv_bfloat162 hzw = __floats2bfloat162_rn(v.z, v.w);
    float2 hf0 = __bfloat1622float2(hxy);
    float2 hf1 = __bfloat1622float2(hzw);
    __nv_bfloat162 lxy = __floats2bfloat162_rn(v.x - hf0.x, v.y - hf0.y);
    __nv_bfloat162 lzw = __floats2bfloat162_rn(v.z - hf1.x, v.w - hf1.y);
    h.x = *(uint32_t*)&hxy; h.y = *(uint32_t*)&hzw;
    l.x = *(uint32_t*)&lxy; l.y = *(uint32_t*)&lzw;
}

// ============================================================================
// Kernel 1: S[n][k] = scale * sum_d q[d][n] * keys[d][k]  via bf16 mma x3.
// ============================================================================
#define DROW 136                         // halfs per d-row
#define QT_BYTES (128 * DROW * 2)        // 34816 per matrix
#define QAHI 0
#define QALO (QT_BYTES)
#define QBHI (2 * QT_BYTES)
#define QBLO (3 * QT_BYTES)
#define SMEM_QK (4 * QT_BYTES)           // 139264

__global__ __launch_bounds__(256, 1) void qk_mma(const float* __restrict__ keys,
                                                 const float* __restrict__ q) {
    extern __shared__ char smem[];
    const uint32_t sb = smem_u32(smem);
    const int tid = threadIdx.x;
    const int lane = tid & 31;
    const int wid = tid >> 5;
    const int g = lane >> 2, tg = lane & 3;
    const int wm = wid & 3;          // warp tile: 32 n
    const int wn = wid >> 2;         // warp tile: 64 k
    const int k0 = blockIdx.x * 128; // bank dim
    const int n0 = blockIdx.y * 128; // query dim
    const float scale = 0.08838834764831845f;

    #pragma unroll
    for (int it = 0; it < 16; it++) {
        int i = it * 256 + tid;
        int d = i >> 5, c4 = (i & 31) * 4;
        uint32_t dst = (uint32_t)(d * DROW + c4) * 2;

        float4 v = make_float4(0.f, 0.f, 0.f, 0.f);
        if (n0 + c4 < NQ) {
            v = *(const float4*)&q[(size_t)d * NQ + n0 + c4];
            v.x *= scale; v.y *= scale; v.z *= scale; v.w *= scale;
        }
        uint2 h, l; split_pack4(v, h, l);
        *(uint2*)(smem + QAHI + dst) = h;
        *(uint2*)(smem + QALO + dst) = l;

        float4 w = make_float4(0.f, 0.f, 0.f, 0.f);
        if (k0 + c4 < BANKN)
            w = *(const float4*)&keys[(size_t)d * BANKN + k0 + c4];
        split_pack4(w, h, l);
        *(uint2*)(smem + QBHI + dst) = h;
        *(uint2*)(smem + QBLO + dst) = l;
    }
    __syncthreads();

    float acc[2][8][4] = {};

    const int a_row_l = (lane & 7) + ((lane >> 4) << 3);
    const int a_col_l = ((lane >> 3) & 1) << 3;
    const int b_row_l = (lane & 7) + (((lane >> 3) & 1) << 3);
    const int b_col_l = (lane >> 4) << 3;

    #pragma unroll
    for (int ks = 0; ks < 8; ks++) {
        const int kk = ks * 16;
        uint32_t ah[2][4], al[2][4];
        #pragma unroll
        for (int mt = 0; mt < 2; mt++) {
            uint32_t off = (uint32_t)((kk + a_row_l) * DROW + wm * 32 + mt * 16 + a_col_l) * 2;
            ldsm_x4t(ah[mt], sb + QAHI + off);
            ldsm_x4t(al[mt], sb + QALO + off);
        }
        #pragma unroll
        for (int p = 0; p < 4; p++) {
            uint32_t off = (uint32_t)((kk + b_row_l) * DROW + wn * 64 + p * 16 + b_col_l) * 2;
            uint32_t bh[4], bl[4];
            ldsm_x4t(bh, sb + QBHI + off);
            ldsm_x4t(bl, sb + QBLO + off);
            #pragma unroll
            for (int mt = 0; mt < 2; mt++) {
                mma_bf16(acc[mt][2 * p],     ah[mt], bh);
                mma_bf16(acc[mt][2 * p],     ah[mt], bl);
                mma_bf16(acc[mt][2 * p],     al[mt], bh);
                mma_bf16(acc[mt][2 * p + 1], ah[mt], bh + 2);
                mma_bf16(acc[mt][2 * p + 1], ah[mt], bl + 2);
                mma_bf16(acc[mt][2 * p + 1], al[mt], bh + 2);
            }
        }
    }

    #pragma unroll
    for (int mt = 0; mt < 2; mt++) {
        int nt_ = n0 + wm * 32 + mt * 16 + g;
        int nb_ = nt_ + 8;
        #pragma unroll
        for (int nt = 0; nt < 8; nt++) {
            int k = k0 + wn * 64 + nt * 8 + tg * 2;
            if (k < BANKN) {
                if (nt_ < NQ)
                    *(float2*)&g_P[(size_t)nt_ * BANKN + k] =
                        make_float2(acc[mt][nt][0], acc[mt][nt][1]);
                if (nb_ < NQ)
                    *(float2*)&g_P[(size_t)nb_ * BANKN + k] =
                        make_float2(acc[mt][nt][2], acc[mt][nt][3]);
            }
        }
    }
}

// ============================================================================
// Kernel 2: row softmax of g_P -> bf16 hi/lo planes, + fused mask dots.
// ============================================================================
__global__ __launch_bounds__(256) void softmax_rows(const float* __restrict__ masks) {
    __shared__ float4 buf4[BANKN / 4];
    __shared__ float  sred[4][8];

    const int tid = threadIdx.x;
    const size_t rbase = (size_t)blockIdx.x * BANKN;
    const float4* r4 = (const float4*)(g_P + rbase);

    float mx = -3.0e38f;
    for (int i = tid; i < BANKN / 4; i += 256) {
        float4 v = r4[i];
        buf4[i] = v;
        mx = fmaxf(mx, fmaxf(fmaxf(v.x, v.y), fmaxf(v.z, v.w)));
    }
    #pragma unroll
    for (int o = 16; o; o >>= 1) mx = fmaxf(mx, __shfl_xor_sync(0xffffffffu, mx, o));
    if ((tid & 31) == 0) sred[0][tid >> 5] = mx;
    __syncthreads();
    mx = sred[0][0];
    #pragma unroll
    for (int w = 1; w < 8; w++) mx = fmaxf(mx, sred[0][w]);
    __syncthreads();

    float sum = 0.f, m0 = 0.f, m1 = 0.f, m2 = 0.f;
    const float4* mk0 = (const float4*)masks;
    const float4* mk1 = (const float4*)(masks + BANKN);
    const float4* mk2 = (const float4*)(masks + 2 * BANKN);
    for (int i = tid; i < BANKN / 4; i += 256) {
        float4 v = buf4[i];
        v.x = __expf(v.x - mx); v.y = __expf(v.y - mx);
        v.z = __expf(v.z - mx); v.w = __expf(v.w - mx);
        buf4[i] = v;
        sum += (v.x + v.y) + (v.z + v.w);
        float4 a = mk0[i], b = mk1[i], c = mk2[i];
        m0 += a.x * v.x + a.y * v.y + a.z * v.z + a.w * v.w;
        m1 += b.x * v.x + b.y * v.y + b.z * v.z + b.w * v.w;
        m2 += c.x * v.x + c.y * v.y + c.z * v.z + c.w * v.w;
    }
    float vals[4] = {sum, m0, m1, m2};
    #pragma unroll
    for (int r = 0; r < 4; r++) {
        float v = vals[r];
        #pragma unroll
        for (int o = 16; o; o >>= 1) v += __shfl_xor_sync(0xffffffffu, v, o);
        if ((tid & 31) == 0) sred[r][tid >> 5] = v;
    }
    __syncthreads();
    float tot = 0.f;
    #pragma unroll
    for (int w = 0; w < 8; w++) tot += sred[0][w];
    const float inv = 1.f / tot;

    if (tid < 3) {
        float t = 0.f;
        #pragma unroll
        for (int w = 0; w < 8; w++) t += sred[tid + 1][w];
        g_mask[tid * NQ + blockIdx.x] = t * inv;
    }

    for (int i = tid; i < BANKN / 4; i += 256) {
        float4 v = buf4[i];
        v.x *= inv; v.y *= inv; v.z *= inv; v.w *= inv;
        uint2 h, l; split_pack4(v, h, l);
        *(uint2*)&g_Ph[rbase + (size_t)i * 4] = h;
        *(uint2*)&g_Pl[rbase + (size_t)i * 4] = l;
    }
}

// ============================================================================
// Kernel 2b: pre-split V into bf16 hi/lo planes (one pass)
// ============================================================================
__global__ __launch_bounds__(256) void conv_v(const float* __restrict__ V) {
    size_t i = (size_t)blockIdx.x * 256 + threadIdx.x;
    const size_t total4 = (size_t)M3 * BANKN / 4;
    if (i >= total4) return;
    float4 v = *(const float4*)&V[i * 4];
    uint2 h, l; split_pack4(v, h, l);
    *(uint2*)&g_Vh[i * 4] = h;
    *(uint2*)&g_Vl[i * 4] = l;
}

// ============================================================================
// Kernel 3: mem[r][n] = sum_k V[r][k] * P[n][k], bf16 mma x3 + ldmatrix.
// R9 tile (128m x 144n) and loop order, but 384 threads / 12 warps
// (3 per SMSP) for latency hiding. Warp grid 4m x 3n -> warp tile 32m x 48n
// (3 clean x4 B pairs). Same smem, same traffic, more concurrency.
// ============================================================================
#define KC 304
#define VTHREADS 384
#define ROWP 40                    // smem row stride in halfs
#define OFF_AHI 0
#define OFF_ALO 10240
#define OFF_BHI 20480
#define OFF_BLO 32000
#define BUF_BYTES 43520
#define SMEM_VAL (2 * BUF_BYTES)   // 87040

struct StageV {
    uint4 ah[2], al[2], bh[2], bl[2];
};

__device__ __forceinline__ void ldg_chunk(int m0, int n0, int k0, int tid, StageV& s) {
    const uint4 z = make_uint4(0, 0, 0, 0);
    // A plane: 512 uint4 (128 rows x 4)
    #pragma unroll
    for (int it = 0; it < 2; it++) {
        int i = it * VTHREADS + tid;
        s.ah[it] = z; s.al[it] = z;
        if (i < 512) {
            int m = i >> 2, kc = (i & 3) * 8;
            if (k0 + kc < BANKN) {
                size_t off = (size_t)(m0 + m) * BANKN + k0 + kc;
                s.ah[it] = *(const uint4*)&g_Vh[off];
                s.al[it] = *(const uint4*)&g_Vl[off];
            }
        }
    }
    // B plane: 576 uint4 (144 rows x 4)
    #pragma unroll
    for (int it = 0; it < 2; it++) {
        int i = it * VTHREADS + tid;
        s.bh[it] = z; s.bl[it] = z;
        if (i < 576) {
            int r = i >> 2, kc = (i & 3) * 8;
            if (n0 + r < NQ && k0 + kc < BANKN) {
                size_t off = (size_t)(n0 + r) * BANKN + k0 + kc;
                s.bh[it] = *(const uint4*)&g_Ph[off];
                s.bl[it] = *(const uint4*)&g_Pl[off];
            }
        }
    }
}

__device__ __forceinline__ void sts_chunk(char* buf, int tid, const StageV& s) {
    #pragma unroll
    for (int it = 0; it < 2; it++) {
        int i = it * VTHREADS + tid;
        if (i < 512) {
            int m = i >> 2, kc = (i & 3) * 8;
            *(uint4*)(buf + OFF_AHI + (m * ROWP + kc) * 2) = s.ah[it];
            *(uint4*)(buf + OFF_ALO + (m * ROWP + kc) * 2) = s.al[it];
        }
    }
    #pragma unroll
    for (int it = 0; it < 2; it++) {
        int i = it * VTHREADS + tid;
        if (i < 576) {
            int r = i >> 2, kc = (i & 3) * 8;
            *(uint4*)(buf + OFF_BHI + (r * ROWP + kc) * 2) = s.bh[it];
            *(uint4*)(buf + OFF_BLO + (r * ROWP + kc) * 2) = s.bl[it];
        }
    }
}

__global__ __launch_bounds__(VTHREADS, 1) void val_gemm_mma(float* __restrict__ out) {
    extern __shared__ char smem[];
    const uint32_t sb = smem_u32(smem);
    const int tid = threadIdx.x;
    const int wid = tid >> 5;
    const int lane = tid & 31;
    const int g = lane >> 2, tg = lane & 3;
    const int wm = wid & 3;            // 4 warps over m (32 each)
    const int wn = wid >> 2;           // 3 warps over n (48 each)
    const int n0 = blockIdx.x * 144;
    const int m0 = blockIdx.y * 128;

    const int av_row = (lane & 7) + (((lane >> 3) & 1) << 3);
    const int av_col = (lane >> 4) << 3;
    const int bv_row = (lane & 7) + ((lane >> 4) << 3);
    const int bv_col = ((lane >> 3) & 1) << 3;

    float acc[2][6][4] = {};

    {
        StageV s;
        ldg_chunk(m0, n0, 0, tid, s);
        sts_chunk(smem, tid, s);
    }
    __syncthreads();

    for (int c = 0; c < KC; c++) {
        const uint32_t boff = (uint32_t)(c & 1) * BUF_BYTES;
        char* nbuf = smem + (size_t)((c + 1) & 1) * BUF_BYTES;

        StageV s;
        const bool more = (c + 1 < KC);
        if (more) ldg_chunk(m0, n0, (c + 1) * 32, tid, s);

        #pragma unroll
        for (int ks = 0; ks < 2; ks++) {
            const int kk = ks * 16;
            uint32_t ah[2][4], al[2][4];
            #pragma unroll
            for (int mt = 0; mt < 2; mt++) {
                uint32_t off = (uint32_t)((wm * 32 + mt * 16 + av_row) * ROWP + kk + av_col) * 2;
                ldsm_x4(ah[mt], sb + boff + OFF_AHI + off);
                ldsm_x4(al[mt], sb + boff + OFF_ALO + off);
            }
            #pragma unroll
            for (int p = 0; p < 3; p++) {
                uint32_t off = (uint32_t)((wn * 48 + p * 16 + bv_row) * ROWP + kk + bv_col) * 2;
                uint32_t bh[4], bl[4];
                ldsm_x4(bh, sb + boff + OFF_BHI + off);
                ldsm_x4(bl, sb + boff + OFF_BLO + off);
                #pragma unroll
                for (int mt = 0; mt < 2; mt++) {
                    mma_bf16(acc[mt][2 * p],     ah[mt], bh);
                    mma_bf16(acc[mt][2 * p],     ah[mt], bl);
                    mma_bf16(acc[mt][2 * p],     al[mt], bh);
                    mma_bf16(acc[mt][2 * p + 1], ah[mt], bh + 2);
                    mma_bf16(acc[mt][2 * p + 1], ah[mt], bl + 2);
                    mma_bf16(acc[mt][2 * p + 1], al[mt], bh + 2);
                }
            }
        }

        if (more) sts_chunk(nbuf, tid, s);
        __syncthreads();
    }

    const int n_base = n0 + wn * 48;
    const int m_base = m0 + wm * 32;
    #pragma unroll
    for (int mt = 0; mt < 2; mt++) {
        int rt = m_base + mt * 16 + g;
        int rb = rt + 8;
        float* row_t = out + (size_t)((rt >> 9) * 1024 + (rt & 511)) * NQ;
        float* row_b = out + (size_t)((rb >> 9) * 1024 + (rb & 511)) * NQ;
        #pragma unroll
        for (int nt = 0; nt < 6; nt++) {
            int n = n_base + nt * 8 + tg * 2;
            if (n < NQ) {
                *(float2*)&row_t[n] = make_float2(acc[mt][nt][0], acc[mt][nt][1]);
                *(float2*)&row_b[n] = make_float2(acc[mt][nt][2], acc[mt][nt][3]);
            }
        }
    }
}

// ============================================================================
// Kernel 4: out[o][512+c][n] = q_out[o][c][n] * mask_mem[o][n]
// ============================================================================
__global__ __launch_bounds__(256) void apply_mask(const float* __restrict__ q_out,
                                                  float* __restrict__ out) {
    int idx = blockIdx.x * 256 + threadIdx.x;
    const int total = OBJN * 512 * NQ;
    if (idx >= total) return;
    int n    = idx % NQ;
    int rest = idx / NQ;
    int c    = rest % 512;
    int o    = rest / 512;
    out[(size_t)(o * 1024 + 512 + c) * NQ + n] = q_out[idx] * g_mask[o * NQ + n];
}

// ============================================================================
extern "C" void kernel_launch(void* const* d_in, const int* in_sizes, int n_in,
                              void* d_out, int out_size) {
    const float* keys   = (const float*)d_in[0];  // (128, 9720)
    const float* q_in   = (const float*)d_in[1];  // (1, 128, 1620)
    const float* q_out  = (const float*)d_in[2];  // (3, 512, 1620)
    const float* values = (const float*)d_in[3];  // (3, 512, 9720)
    const float* masks  = (const float*)d_in[4];  // (3, 1, 9720)
    float* out = (float*)d_out;                   // (1, 3, 1024, 1620)

    (void)in_sizes; (void)n_in; (void)out_size;

    cudaFuncSetAttribute(qk_mma, cudaFuncAttributeMaxDynamicSharedMemorySize, SMEM_QK);
    cudaFuncSetAttribute(val_gemm_mma, cudaFuncAttributeMaxDynamicSharedMemorySize, SMEM_VAL);

    dim3 g1((BANKN + 127) / 128, (NQ + 127) / 128);   // 76 x 13
    qk_mma<<<g1, 256, SMEM_QK>>>(keys, q_in);         // launch 0

    softmax_rows<<<NQ, 256>>>(masks);                 // launch 1

    const int convN = (int)(((size_t)M3 * BANKN / 4 + 255) / 256);
    conv_v<<<convN, 256>>>(values);                   // launch 2 (independent)

    dim3 g3(12, 12);                                  // one wave, 144 CTAs
    val_gemm_mma<<<g3, VTHREADS, SMEM_VAL>>>(out);    // launch 3 (profiled slot)

    apply_mask<<<(OBJN * 512 * NQ + 255) / 256, 256>>>(q_out, out);  // launch 4
}

// round 15
// speedup vs baseline: 1.5551x; 1.3171x over previous
#include <cuda_runtime.h>
#include <cuda_bf16.h>
#include <cuda_fp16.h>
#include <cstdint>

#define D_KEYC 128
#define BANKN  9720
#define NQ     1620
#define OBJN   3
#define M3     1536

// Scratch (device globals — no allocation allowed)
__device__ float g_P[(size_t)NQ * BANKN];              // fp32 logits
__device__ __half g_P16[(size_t)NQ * BANKN];           // softmax probs, fp16
__device__ __half g_V16h[(size_t)M3 * BANKN];          // values, fp16 hi plane
__device__ __half g_V16l[(size_t)M3 * BANKN];          // values, fp16 lo plane
__device__ float g_mask[OBJN * NQ];                    // mask_mem[o][n]

// ============================================================================
// Common helpers
// ============================================================================
__device__ __forceinline__ uint32_t smem_u32(const void* p) {
    uint32_t a;
    asm("{ .reg .u64 t; cvta.to.shared.u64 t, %1; cvt.u32.u64 %0, t; }"
        : "=r"(a) : "l"(p));
    return a;
}

__device__ __forceinline__ void mma_bf16(float* d, const uint32_t* a, const uint32_t* b) {
    asm volatile(
        "mma.sync.aligned.m16n8k16.row.col.f32.bf16.bf16.f32 "
        "{%0,%1,%2,%3}, {%4,%5,%6,%7}, {%8,%9}, {%0,%1,%2,%3};"
        : "+f"(d[0]), "+f"(d[1]), "+f"(d[2]), "+f"(d[3])
        : "r"(a[0]), "r"(a[1]), "r"(a[2]), "r"(a[3]), "r"(b[0]), "r"(b[1]));
}

__device__ __forceinline__ void mma_f16(float* d, const uint32_t* a, const uint32_t* b) {
    asm volatile(
        "mma.sync.aligned.m16n8k16.row.col.f32.f16.f16.f32 "
        "{%0,%1,%2,%3}, {%4,%5,%6,%7}, {%8,%9}, {%0,%1,%2,%3};"
        : "+f"(d[0]), "+f"(d[1]), "+f"(d[2]), "+f"(d[3])
        : "r"(a[0]), "r"(a[1]), "r"(a[2]), "r"(a[3]), "r"(b[0]), "r"(b[1]));
}

__device__ __forceinline__ void ldsm_x4(uint32_t* r, uint32_t addr) {
    asm volatile("ldmatrix.sync.aligned.m8n8.x4.shared.b16 {%0,%1,%2,%3}, [%4];"
                 : "=r"(r[0]), "=r"(r[1]), "=r"(r[2]), "=r"(r[3]) : "r"(addr));
}
__device__ __forceinline__ void ldsm_x4t(uint32_t* r, uint32_t addr) {
    asm volatile("ldmatrix.sync.aligned.m8n8.x4.trans.shared.b16 {%0,%1,%2,%3}, [%4];"
                 : "=r"(r[0]), "=r"(r[1]), "=r"(r[2]), "=r"(r[3]) : "r"(addr));
}
__device__ __forceinline__ void ldsm_x2(uint32_t* r, uint32_t addr) {
    asm volatile("ldmatrix.sync.aligned.m8n8.x2.shared.b16 {%0,%1}, [%2];"
                 : "=r"(r[0]), "=r"(r[1]) : "r"(addr));
}

// split fp32 -> bf16 hi + bf16 lo (for qk_mma)
__device__ __forceinline__ void split_pack4(float4 v, uint2& h, uint2& l) {
    __nv_bfloat162 hxy = __floats2bfloat162_rn(v.x, v.y);
    __nv_bfloat162 hzw = __floats2bfloat162_rn(v.z, v.w);
    float2 hf0 = __bfloat1622float2(hxy);
    float2 hf1 = __bfloat1622float2(hzw);
    __nv_bfloat162 lxy = __floats2bfloat162_rn(v.x - hf0.x, v.y - hf0.y);
    __nv_bfloat162 lzw = __floats2bfloat162_rn(v.z - hf1.x, v.w - hf1.y);
    h.x = *(uint32_t*)&hxy; h.y = *(uint32_t*)&hzw;
    l.x = *(uint32_t*)&lxy; l.y = *(uint32_t*)&lzw;
}

// split fp32 -> fp16 hi + fp16 lo (residual ~2^-22, for values)
__device__ __forceinline__ void split_pack4_f16(float4 v, uint2& h, uint2& l) {
    __half2 h01 = __floats2half2_rn(v.x, v.y);
    __half2 h23 = __floats2half2_rn(v.z, v.w);
    float2 f01 = __half22float2(h01);
    float2 f23 = __half22float2(h23);
    __half2 l01 = __floats2half2_rn(v.x - f01.x, v.y - f01.y);
    __half2 l23 = __floats2half2_rn(v.z - f23.x, v.w - f23.y);
    h.x = *(uint32_t*)&h01; h.y = *(uint32_t*)&h23;
    l.x = *(uint32_t*)&l01; l.y = *(uint32_t*)&l23;
}

// ============================================================================
// Kernel 1: S[n][k] = scale * sum_d q[d][n] * keys[d][k]  via bf16 mma x3.
// (unchanged from champion)
// ============================================================================
#define DROW 136
#define QT_BYTES (128 * DROW * 2)
#define QAHI 0
#define QALO (QT_BYTES)
#define QBHI (2 * QT_BYTES)
#define QBLO (3 * QT_BYTES)
#define SMEM_QK (4 * QT_BYTES)           // 139264

__global__ __launch_bounds__(256, 1) void qk_mma(const float* __restrict__ keys,
                                                 const float* __restrict__ q) {
    extern __shared__ char smem[];
    const uint32_t sb = smem_u32(smem);
    const int tid = threadIdx.x;
    const int lane = tid & 31;
    const int wid = tid >> 5;
    const int g = lane >> 2, tg = lane & 3;
    const int wm = wid & 3;
    const int wn = wid >> 2;
    const int k0 = blockIdx.x * 128;
    const int n0 = blockIdx.y * 128;
    const float scale = 0.08838834764831845f;

    #pragma unroll
    for (int it = 0; it < 16; it++) {
        int i = it * 256 + tid;
        int d = i >> 5, c4 = (i & 31) * 4;
        uint32_t dst = (uint32_t)(d * DROW + c4) * 2;

        float4 v = make_float4(0.f, 0.f, 0.f, 0.f);
        if (n0 + c4 < NQ) {
            v = *(const float4*)&q[(size_t)d * NQ + n0 + c4];
            v.x *= scale; v.y *= scale; v.z *= scale; v.w *= scale;
        }
        uint2 h, l; split_pack4(v, h, l);
        *(uint2*)(smem + QAHI + dst) = h;
        *(uint2*)(smem + QALO + dst) = l;

        float4 w = make_float4(0.f, 0.f, 0.f, 0.f);
        if (k0 + c4 < BANKN)
            w = *(const float4*)&keys[(size_t)d * BANKN + k0 + c4];
        split_pack4(w, h, l);
        *(uint2*)(smem + QBHI + dst) = h;
        *(uint2*)(smem + QBLO + dst) = l;
    }
    __syncthreads();

    float acc[2][8][4] = {};

    const int a_row_l = (lane & 7) + ((lane >> 4) << 3);
    const int a_col_l = ((lane >> 3) & 1) << 3;
    const int b_row_l = (lane & 7) + (((lane >> 3) & 1) << 3);
    const int b_col_l = (lane >> 4) << 3;

    #pragma unroll
    for (int ks = 0; ks < 8; ks++) {
        const int kk = ks * 16;
        uint32_t ah[2][4], al[2][4];
        #pragma unroll
        for (int mt = 0; mt < 2; mt++) {
            uint32_t off = (uint32_t)((kk + a_row_l) * DROW + wm * 32 + mt * 16 + a_col_l) * 2;
            ldsm_x4t(ah[mt], sb + QAHI + off);
            ldsm_x4t(al[mt], sb + QALO + off);
        }
        #pragma unroll
        for (int p = 0; p < 4; p++) {
            uint32_t off = (uint32_t)((kk + b_row_l) * DROW + wn * 64 + p * 16 + b_col_l) * 2;
            uint32_t bh[4], bl[4];
            ldsm_x4t(bh, sb + QBHI + off);
            ldsm_x4t(bl, sb + QBLO + off);
            #pragma unroll
            for (int mt = 0; mt < 2; mt++) {
                mma_bf16(acc[mt][2 * p],     ah[mt], bh);
                mma_bf16(acc[mt][2 * p],     ah[mt], bl);
                mma_bf16(acc[mt][2 * p],     al[mt], bh);
                mma_bf16(acc[mt][2 * p + 1], ah[mt], bh + 2);
                mma_bf16(acc[mt][2 * p + 1], ah[mt], bl + 2);
                mma_bf16(acc[mt][2 * p + 1], al[mt], bh + 2);
            }
        }
    }

    #pragma unroll
    for (int mt = 0; mt < 2; mt++) {
        int nt_ = n0 + wm * 32 + mt * 16 + g;
        int nb_ = nt_ + 8;
        #pragma unroll
        for (int nt = 0; nt < 8; nt++) {
            int k = k0 + wn * 64 + nt * 8 + tg * 2;
            if (k < BANKN) {
                if (nt_ < NQ)
                    *(float2*)&g_P[(size_t)nt_ * BANKN + k] =
                        make_float2(acc[mt][nt][0], acc[mt][nt][1]);
                if (nb_ < NQ)
                    *(float2*)&g_P[(size_t)nb_ * BANKN + k] =
                        make_float2(acc[mt][nt][2], acc[mt][nt][3]);
            }
        }
    }
}

// ============================================================================
// Kernel 2: row softmax of g_P -> single fp16 plane, + fused mask dots.
// ============================================================================
__global__ __launch_bounds__(256) void softmax_rows(const float* __restrict__ masks) {
    __shared__ float4 buf4[BANKN / 4];
    __shared__ float  sred[4][8];

    const int tid = threadIdx.x;
    const size_t rbase = (size_t)blockIdx.x * BANKN;
    const float4* r4 = (const float4*)(g_P + rbase);

    float mx = -3.0e38f;
    for (int i = tid; i < BANKN / 4; i += 256) {
        float4 v = r4[i];
        buf4[i] = v;
        mx = fmaxf(mx, fmaxf(fmaxf(v.x, v.y), fmaxf(v.z, v.w)));
    }
    #pragma unroll
    for (int o = 16; o; o >>= 1) mx = fmaxf(mx, __shfl_xor_sync(0xffffffffu, mx, o));
    if ((tid & 31) == 0) sred[0][tid >> 5] = mx;
    __syncthreads();
    mx = sred[0][0];
    #pragma unroll
    for (int w = 1; w < 8; w++) mx = fmaxf(mx, sred[0][w]);
    __syncthreads();

    float sum = 0.f, m0 = 0.f, m1 = 0.f, m2 = 0.f;
    const float4* mk0 = (const float4*)masks;
    const float4* mk1 = (const float4*)(masks + BANKN);
    const float4* mk2 = (const float4*)(masks + 2 * BANKN);
    for (int i = tid; i < BANKN / 4; i += 256) {
        float4 v = buf4[i];
        v.x = __expf(v.x - mx); v.y = __expf(v.y - mx);
        v.z = __expf(v.z - mx); v.w = __expf(v.w - mx);
        buf4[i] = v;
        sum += (v.x + v.y) + (v.z + v.w);
        float4 a = mk0[i], b = mk1[i], c = mk2[i];
        m0 += a.x * v.x + a.y * v.y + a.z * v.z + a.w * v.w;
        m1 += b.x * v.x + b.y * v.y + b.z * v.z + b.w * v.w;
        m2 += c.x * v.x + c.y * v.y + c.z * v.z + c.w * v.w;
    }
    float vals[4] = {sum, m0, m1, m2};
    #pragma unroll
    for (int r = 0; r < 4; r++) {
        float v = vals[r];
        #pragma unroll
        for (int o = 16; o; o >>= 1) v += __shfl_xor_sync(0xffffffffu, v, o);
        if ((tid & 31) == 0) sred[r][tid >> 5] = v;
    }
    __syncthreads();
    float tot = 0.f;
    #pragma unroll
    for (int w = 0; w < 8; w++) tot += sred[0][w];
    const float inv = 1.f / tot;

    if (tid < 3) {
        float t = 0.f;
        #pragma unroll
        for (int w = 0; w < 8; w++) t += sred[tid + 1][w];
        g_mask[tid * NQ + blockIdx.x] = t * inv;
    }

    for (int i = tid; i < BANKN / 4; i += 256) {
        float4 v = buf4[i];
        __half2 p01 = __floats2half2_rn(v.x * inv, v.y * inv);
        __half2 p23 = __floats2half2_rn(v.z * inv, v.w * inv);
        uint2 u;
        u.x = *(uint32_t*)&p01; u.y = *(uint32_t*)&p23;
        *(uint2*)&g_P16[rbase + (size_t)i * 4] = u;
    }
}

// ============================================================================
// Kernel 2b: pre-split V into fp16 hi/lo planes (one pass)
// ============================================================================
__global__ __launch_bounds__(256) void conv_v(const float* __restrict__ V) {
    size_t i = (size_t)blockIdx.x * 256 + threadIdx.x;
    const size_t total4 = (size_t)M3 * BANKN / 4;
    if (i >= total4) return;
    float4 v = *(const float4*)&V[i * 4];
    uint2 h, l; split_pack4_f16(v, h, l);
    *(uint2*)&g_V16h[i * 4] = h;
    *(uint2*)&g_V16l[i * 4] = l;
}

// ============================================================================
// Kernel 3: mem[r][n] = sum_k V[r][k] * P[n][k], fp16 mma x2 + ldmatrix.
//   mem = Vh*P + Vl*P   (V split exact to 2^-22; P fp16-quantized, ~1e-4 out)
// R9 geometry/loop order: 128m x 144n, 8 warps 4m x 2n, K-chunk 32,
// grid 12x12 one wave, double buffered. 3 smem planes instead of 4.
// ============================================================================
#define KC 304
#define ROWP 40                    // smem row stride in halfs
#define OFF_AH 0
#define OFF_AL 10240               // 128*40*2
#define OFF_B  20480
#define BUF_BYTES 32000            // 20480 + 144*40*2
#define SMEM_VAL (2 * BUF_BYTES)   // 64000

struct StageV {
    uint4 ah[2], al[2], b[3];
};

__device__ __forceinline__ void ldg_chunk(int m0, int n0, int k0, int tid, StageV& s) {
    const uint4 z = make_uint4(0, 0, 0, 0);
    #pragma unroll
    for (int it = 0; it < 2; it++) {
        int i = it * 256 + tid;
        int m = i >> 2, kc = (i & 3) * 8;
        if (k0 + kc < BANKN) {
            size_t off = (size_t)(m0 + m) * BANKN + k0 + kc;
            s.ah[it] = *(const uint4*)&g_V16h[off];
            s.al[it] = *(const uint4*)&g_V16l[off];
        } else { s.ah[it] = z; s.al[it] = z; }
    }
    #pragma unroll
    for (int it = 0; it < 3; it++) {
        int i = it * 256 + tid;
        s.b[it] = z;
        if (i < 576) {
            int r = i >> 2, kc = (i & 3) * 8;
            if (n0 + r < NQ && k0 + kc < BANKN)
                s.b[it] = *(const uint4*)&g_P16[(size_t)(n0 + r) * BANKN + k0 + kc];
        }
    }
}

__device__ __forceinline__ void sts_chunk(char* buf, int tid, const StageV& s) {
    #pragma unroll
    for (int it = 0; it < 2; it++) {
        int i = it * 256 + tid;
        int m = i >> 2, kc = (i & 3) * 8;
        *(uint4*)(buf + OFF_AH + (m * ROWP + kc) * 2) = s.ah[it];
        *(uint4*)(buf + OFF_AL + (m * ROWP + kc) * 2) = s.al[it];
    }
    #pragma unroll
    for (int it = 0; it < 3; it++) {
        int i = it * 256 + tid;
        if (i < 576) {
            int r = i >> 2, kc = (i & 3) * 8;
            *(uint4*)(buf + OFF_B + (r * ROWP + kc) * 2) = s.b[it];
        }
    }
}

__global__ __launch_bounds__(256, 1) void val_gemm_mma(float* __restrict__ out) {
    extern __shared__ char smem[];
    const uint32_t sb = smem_u32(smem);
    const int tid = threadIdx.x;
    const int wid = tid >> 5;
    const int lane = tid & 31;
    const int g = lane >> 2, tg = lane & 3;
    const int wm = wid & 3;
    const int wn = wid >> 2;
    const int n0 = blockIdx.x * 144;
    const int m0 = blockIdx.y * 128;

    const int av_row = (lane & 7) + (((lane >> 3) & 1) << 3);
    const int av_col = (lane >> 4) << 3;
    const int bv_row = (lane & 7) + ((lane >> 4) << 3);
    const int bv_col = ((lane >> 3) & 1) << 3;
    const int b2_row = lane & 7;
    const int b2_col = ((lane >> 3) & 1) << 3;

    float acc[2][9][4] = {};

    {
        StageV s;
        ldg_chunk(m0, n0, 0, tid, s);
        sts_chunk(smem, tid, s);
    }
    __syncthreads();

    for (int c = 0; c < KC; c++) {
        const uint32_t boff = (uint32_t)(c & 1) * BUF_BYTES;
        char* nbuf = smem + (size_t)((c + 1) & 1) * BUF_BYTES;

        StageV s;
        const bool more = (c + 1 < KC);
        if (more) ldg_chunk(m0, n0, (c + 1) * 32, tid, s);

        #pragma unroll
        for (int ks = 0; ks < 2; ks++) {
            const int kk = ks * 16;
            uint32_t ah[2][4], al[2][4];
            #pragma unroll
            for (int mt = 0; mt < 2; mt++) {
                uint32_t off = (uint32_t)((wm * 32 + mt * 16 + av_row) * ROWP + kk + av_col) * 2;
                ldsm_x4(ah[mt], sb + boff + OFF_AH + off);
                ldsm_x4(al[mt], sb + boff + OFF_AL + off);
            }
            #pragma unroll
            for (int p = 0; p < 4; p++) {
                uint32_t off = (uint32_t)((wn * 72 + p * 16 + bv_row) * ROWP + kk + bv_col) * 2;
                uint32_t b[4];
                ldsm_x4(b, sb + boff + OFF_B + off);
                #pragma unroll
                for (int mt = 0; mt < 2; mt++) {
                    mma_f16(acc[mt][2 * p],     ah[mt], b);
                    mma_f16(acc[mt][2 * p],     al[mt], b);
                    mma_f16(acc[mt][2 * p + 1], ah[mt], b + 2);
                    mma_f16(acc[mt][2 * p + 1], al[mt], b + 2);
                }
            }
            {   // leftover nt = 8
                uint32_t off = (uint32_t)((wn * 72 + 64 + b2_row) * ROWP + kk + b2_col) * 2;
                uint32_t b2[2];
                ldsm_x2(b2, sb + boff + OFF_B + off);
                #pragma unroll
                for (int mt = 0; mt < 2; mt++) {
                    mma_f16(acc[mt][8], ah[mt], b2);
                    mma_f16(acc[mt][8], al[mt], b2);
                }
            }
        }

        if (more) sts_chunk(nbuf, tid, s);
        __syncthreads();
    }

    const int n_base = n0 + wn * 72;
    const int m_base = m0 + wm * 32;
    #pragma unroll
    for (int mt = 0; mt < 2; mt++) {
        int rt = m_base + mt * 16 + g;
        int rb = rt + 8;
        float* row_t = out + (size_t)((rt >> 9) * 1024 + (rt & 511)) * NQ;
        float* row_b = out + (size_t)((rb >> 9) * 1024 + (rb & 511)) * NQ;
        #pragma unroll
        for (int nt = 0; nt < 9; nt++) {
            int n = n_base + nt * 8 + tg * 2;
            if (n < NQ) {
                *(float2*)&row_t[n] = make_float2(acc[mt][nt][0], acc[mt][nt][1]);
                *(float2*)&row_b[n] = make_float2(acc[mt][nt][2], acc[mt][nt][3]);
            }
        }
    }
}

// ============================================================================
// Kernel 4: out[o][512+c][n] = q_out[o][c][n] * mask_mem[o][n]
// ============================================================================
__global__ __launch_bounds__(256) void apply_mask(const float* __restrict__ q_out,
                                                  float* __restrict__ out) {
    int idx = blockIdx.x * 256 + threadIdx.x;
    const int total = OBJN * 512 * NQ;
    if (idx >= total) return;
    int n    = idx % NQ;
    int rest = idx / NQ;
    int c    = rest % 512;
    int o    = rest / 512;
    out[(size_t)(o * 1024 + 512 + c) * NQ + n] = q_out[idx] * g_mask[o * NQ + n];
}

// ============================================================================
extern "C" void kernel_launch(void* const* d_in, const int* in_sizes, int n_in,
                              void* d_out, int out_size) {
    const float* keys   = (const float*)d_in[0];  // (128, 9720)
    const float* q_in   = (const float*)d_in[1];  // (1, 128, 1620)
    const float* q_out  = (const float*)d_in[2];  // (3, 512, 1620)
    const float* values = (const float*)d_in[3];  // (3, 512, 9720)
    const float* masks  = (const float*)d_in[4];  // (3, 1, 9720)
    float* out = (float*)d_out;                   // (1, 3, 1024, 1620)

    (void)in_sizes; (void)n_in; (void)out_size;

    cudaFuncSetAttribute(qk_mma, cudaFuncAttributeMaxDynamicSharedMemorySize, SMEM_QK);
    cudaFuncSetAttribute(val_gemm_mma, cudaFuncAttributeMaxDynamicSharedMemorySize, SMEM_VAL);

    dim3 g1((BANKN + 127) / 128, (NQ + 127) / 128);   // 76 x 13
    qk_mma<<<g1, 256, SMEM_QK>>>(keys, q_in);         // launch 0

    softmax_rows<<<NQ, 256>>>(masks);                 // launch 1

    const int convN = (int)(((size_t)M3 * BANKN / 4 + 255) / 256);
    conv_v<<<convN, 256>>>(values);                   // launch 2 (independent)

    dim3 g3(12, 12);                                  // one wave, 144 CTAs
    val_gemm_mma<<<g3, 256, SMEM_VAL>>>(out);         // launch 3 (profiled slot)

    apply_mask<<<(OBJN * 512 * NQ + 255) / 256, 256>>>(q_out, out);  // launch 4
}

// round 16
// speedup vs baseline: 1.7900x; 1.1511x over previous
#include <cuda_runtime.h>
#include <cuda_bf16.h>
#include <cuda_fp16.h>
#include <cstdint>

#define D_KEYC 128
#define BANKN  9720
#define NQ     1620
#define OBJN   3
#define M3     1536

// Scratch (device globals — no allocation allowed)
__device__ float g_P[(size_t)NQ * BANKN];              // fp32 logits
__device__ __half g_P16[(size_t)NQ * BANKN];           // softmax probs, fp16
__device__ __half g_V16[(size_t)M3 * BANKN];           // values, fp16
__device__ float g_mask[OBJN * NQ];                    // mask_mem[o][n]

// ============================================================================
// Common helpers
// ============================================================================
__device__ __forceinline__ uint32_t smem_u32(const void* p) {
    uint32_t a;
    asm("{ .reg .u64 t; cvta.to.shared.u64 t, %1; cvt.u32.u64 %0, t; }"
        : "=r"(a) : "l"(p));
    return a;
}

__device__ __forceinline__ void mma_bf16(float* d, const uint32_t* a, const uint32_t* b) {
    asm volatile(
        "mma.sync.aligned.m16n8k16.row.col.f32.bf16.bf16.f32 "
        "{%0,%1,%2,%3}, {%4,%5,%6,%7}, {%8,%9}, {%0,%1,%2,%3};"
        : "+f"(d[0]), "+f"(d[1]), "+f"(d[2]), "+f"(d[3])
        : "r"(a[0]), "r"(a[1]), "r"(a[2]), "r"(a[3]), "r"(b[0]), "r"(b[1]));
}

__device__ __forceinline__ void mma_f16(float* d, const uint32_t* a, const uint32_t* b) {
    asm volatile(
        "mma.sync.aligned.m16n8k16.row.col.f32.f16.f16.f32 "
        "{%0,%1,%2,%3}, {%4,%5,%6,%7}, {%8,%9}, {%0,%1,%2,%3};"
        : "+f"(d[0]), "+f"(d[1]), "+f"(d[2]), "+f"(d[3])
        : "r"(a[0]), "r"(a[1]), "r"(a[2]), "r"(a[3]), "r"(b[0]), "r"(b[1]));
}

__device__ __forceinline__ void ldsm_x4(uint32_t* r, uint32_t addr) {
    asm volatile("ldmatrix.sync.aligned.m8n8.x4.shared.b16 {%0,%1,%2,%3}, [%4];"
                 : "=r"(r[0]), "=r"(r[1]), "=r"(r[2]), "=r"(r[3]) : "r"(addr));
}
__device__ __forceinline__ void ldsm_x4t(uint32_t* r, uint32_t addr) {
    asm volatile("ldmatrix.sync.aligned.m8n8.x4.trans.shared.b16 {%0,%1,%2,%3}, [%4];"
                 : "=r"(r[0]), "=r"(r[1]), "=r"(r[2]), "=r"(r[3]) : "r"(addr));
}
__device__ __forceinline__ void ldsm_x2(uint32_t* r, uint32_t addr) {
    asm volatile("ldmatrix.sync.aligned.m8n8.x2.shared.b16 {%0,%1}, [%2];"
                 : "=r"(r[0]), "=r"(r[1]) : "r"(addr));
}

// split fp32 -> bf16 hi + bf16 lo (for qk_mma)
__device__ __forceinline__ void split_pack4(float4 v, uint2& h, uint2& l) {
    __nv_bfloat162 hxy = __floats2bfloat162_rn(v.x, v.y);
    __nv_bfloat162 hzw = __floats2bfloat162_rn(v.z, v.w);
    float2 hf0 = __bfloat1622float2(hxy);
    float2 hf1 = __bfloat1622float2(hzw);
    __nv_bfloat162 lxy = __floats2bfloat162_rn(v.x - hf0.x, v.y - hf0.y);
    __nv_bfloat162 lzw = __floats2bfloat162_rn(v.z - hf1.x, v.w - hf1.y);
    h.x = *(uint32_t*)&hxy; h.y = *(uint32_t*)&hzw;
    l.x = *(uint32_t*)&lxy; l.y = *(uint32_t*)&lzw;
}

// ============================================================================
// Kernel 1: S[n][k] = scale * sum_d q[d][n] * keys[d][k]  via bf16 mma x3.
// (unchanged from champion — logits need full accuracy for softmax)
// ============================================================================
#define DROW 136
#define QT_BYTES (128 * DROW * 2)
#define QAHI 0
#define QALO (QT_BYTES)
#define QBHI (2 * QT_BYTES)
#define QBLO (3 * QT_BYTES)
#define SMEM_QK (4 * QT_BYTES)           // 139264

__global__ __launch_bounds__(256, 1) void qk_mma(const float* __restrict__ keys,
                                                 const float* __restrict__ q) {
    extern __shared__ char smem[];
    const uint32_t sb = smem_u32(smem);
    const int tid = threadIdx.x;
    const int lane = tid & 31;
    const int wid = tid >> 5;
    const int g = lane >> 2, tg = lane & 3;
    const int wm = wid & 3;
    const int wn = wid >> 2;
    const int k0 = blockIdx.x * 128;
    const int n0 = blockIdx.y * 128;
    const float scale = 0.08838834764831845f;

    #pragma unroll
    for (int it = 0; it < 16; it++) {
        int i = it * 256 + tid;
        int d = i >> 5, c4 = (i & 31) * 4;
        uint32_t dst = (uint32_t)(d * DROW + c4) * 2;

        float4 v = make_float4(0.f, 0.f, 0.f, 0.f);
        if (n0 + c4 < NQ) {
            v = *(const float4*)&q[(size_t)d * NQ + n0 + c4];
            v.x *= scale; v.y *= scale; v.z *= scale; v.w *= scale;
        }
        uint2 h, l; split_pack4(v, h, l);
        *(uint2*)(smem + QAHI + dst) = h;
        *(uint2*)(smem + QALO + dst) = l;

        float4 w = make_float4(0.f, 0.f, 0.f, 0.f);
        if (k0 + c4 < BANKN)
            w = *(const float4*)&keys[(size_t)d * BANKN + k0 + c4];
        split_pack4(w, h, l);
        *(uint2*)(smem + QBHI + dst) = h;
        *(uint2*)(smem + QBLO + dst) = l;
    }
    __syncthreads();

    float acc[2][8][4] = {};

    const int a_row_l = (lane & 7) + ((lane >> 4) << 3);
    const int a_col_l = ((lane >> 3) & 1) << 3;
    const int b_row_l = (lane & 7) + (((lane >> 3) & 1) << 3);
    const int b_col_l = (lane >> 4) << 3;

    #pragma unroll
    for (int ks = 0; ks < 8; ks++) {
        const int kk = ks * 16;
        uint32_t ah[2][4], al[2][4];
        #pragma unroll
        for (int mt = 0; mt < 2; mt++) {
            uint32_t off = (uint32_t)((kk + a_row_l) * DROW + wm * 32 + mt * 16 + a_col_l) * 2;
            ldsm_x4t(ah[mt], sb + QAHI + off);
            ldsm_x4t(al[mt], sb + QALO + off);
        }
        #pragma unroll
        for (int p = 0; p < 4; p++) {
            uint32_t off = (uint32_t)((kk + b_row_l) * DROW + wn * 64 + p * 16 + b_col_l) * 2;
            uint32_t bh[4], bl[4];
            ldsm_x4t(bh, sb + QBHI + off);
            ldsm_x4t(bl, sb + QBLO + off);
            #pragma unroll
            for (int mt = 0; mt < 2; mt++) {
                mma_bf16(acc[mt][2 * p],     ah[mt], bh);
                mma_bf16(acc[mt][2 * p],     ah[mt], bl);
                mma_bf16(acc[mt][2 * p],     al[mt], bh);
                mma_bf16(acc[mt][2 * p + 1], ah[mt], bh + 2);
                mma_bf16(acc[mt][2 * p + 1], ah[mt], bl + 2);
                mma_bf16(acc[mt][2 * p + 1], al[mt], bh + 2);
            }
        }
    }

    #pragma unroll
    for (int mt = 0; mt < 2; mt++) {
        int nt_ = n0 + wm * 32 + mt * 16 + g;
        int nb_ = nt_ + 8;
        #pragma unroll
        for (int nt = 0; nt < 8; nt++) {
            int k = k0 + wn * 64 + nt * 8 + tg * 2;
            if (k < BANKN) {
                if (nt_ < NQ)
                    *(float2*)&g_P[(size_t)nt_ * BANKN + k] =
                        make_float2(acc[mt][nt][0], acc[mt][nt][1]);
                if (nb_ < NQ)
                    *(float2*)&g_P[(size_t)nb_ * BANKN + k] =
                        make_float2(acc[mt][nt][2], acc[mt][nt][3]);
            }
        }
    }
}

// ============================================================================
// Kernel 2: row softmax of g_P -> single fp16 plane, + fused mask dots.
// ============================================================================
__global__ __launch_bounds__(256) void softmax_rows(const float* __restrict__ masks) {
    __shared__ float4 buf4[BANKN / 4];
    __shared__ float  sred[4][8];

    const int tid = threadIdx.x;
    const size_t rbase = (size_t)blockIdx.x * BANKN;
    const float4* r4 = (const float4*)(g_P + rbase);

    float mx = -3.0e38f;
    for (int i = tid; i < BANKN / 4; i += 256) {
        float4 v = r4[i];
        buf4[i] = v;
        mx = fmaxf(mx, fmaxf(fmaxf(v.x, v.y), fmaxf(v.z, v.w)));
    }
    #pragma unroll
    for (int o = 16; o; o >>= 1) mx = fmaxf(mx, __shfl_xor_sync(0xffffffffu, mx, o));
    if ((tid & 31) == 0) sred[0][tid >> 5] = mx;
    __syncthreads();
    mx = sred[0][0];
    #pragma unroll
    for (int w = 1; w < 8; w++) mx = fmaxf(mx, sred[0][w]);
    __syncthreads();

    float sum = 0.f, m0 = 0.f, m1 = 0.f, m2 = 0.f;
    const float4* mk0 = (const float4*)masks;
    const float4* mk1 = (const float4*)(masks + BANKN);
    const float4* mk2 = (const float4*)(masks + 2 * BANKN);
    for (int i = tid; i < BANKN / 4; i += 256) {
        float4 v = buf4[i];
        v.x = __expf(v.x - mx); v.y = __expf(v.y - mx);
        v.z = __expf(v.z - mx); v.w = __expf(v.w - mx);
        buf4[i] = v;
        sum += (v.x + v.y) + (v.z + v.w);
        float4 a = mk0[i], b = mk1[i], c = mk2[i];
        m0 += a.x * v.x + a.y * v.y + a.z * v.z + a.w * v.w;
        m1 += b.x * v.x + b.y * v.y + b.z * v.z + b.w * v.w;
        m2 += c.x * v.x + c.y * v.y + c.z * v.z + c.w * v.w;
    }
    float vals[4] = {sum, m0, m1, m2};
    #pragma unroll
    for (int r = 0; r < 4; r++) {
        float v = vals[r];
        #pragma unroll
        for (int o = 16; o; o >>= 1) v += __shfl_xor_sync(0xffffffffu, v, o);
        if ((tid & 31) == 0) sred[r][tid >> 5] = v;
    }
    __syncthreads();
    float tot = 0.f;
    #pragma unroll
    for (int w = 0; w < 8; w++) tot += sred[0][w];
    const float inv = 1.f / tot;

    if (tid < 3) {
        float t = 0.f;
        #pragma unroll
        for (int w = 0; w < 8; w++) t += sred[tid + 1][w];
        g_mask[tid * NQ + blockIdx.x] = t * inv;
    }

    for (int i = tid; i < BANKN / 4; i += 256) {
        float4 v = buf4[i];
        __half2 p01 = __floats2half2_rn(v.x * inv, v.y * inv);
        __half2 p23 = __floats2half2_rn(v.z * inv, v.w * inv);
        uint2 u;
        u.x = *(uint32_t*)&p01; u.y = *(uint32_t*)&p23;
        *(uint2*)&g_P16[rbase + (size_t)i * 4] = u;
    }
}

// ============================================================================
// Kernel 2b: convert V to a single fp16 plane (one pass)
// ============================================================================
__global__ __launch_bounds__(256) void conv_v(const float* __restrict__ V) {
    size_t i = (size_t)blockIdx.x * 256 + threadIdx.x;
    const size_t total4 = (size_t)M3 * BANKN / 4;
    if (i >= total4) return;
    float4 v = *(const float4*)&V[i * 4];
    __half2 h01 = __floats2half2_rn(v.x, v.y);
    __half2 h23 = __floats2half2_rn(v.z, v.w);
    uint2 u;
    u.x = *(uint32_t*)&h01; u.y = *(uint32_t*)&h23;
    *(uint2*)&g_V16[i * 4] = u;
}

// ============================================================================
// Kernel 3: mem[r][n] = sum_k V[r][k] * P[n][k], plain fp16 mma + ldmatrix.
// V and P both fp16 (error lands ~1e-5 global; mem part is small vs q_out
// part of the output norm — validated by R15 measurement).
// R9 geometry/loop order: 128m x 144n, 8 warps 4m x 2n, K-chunk 32,
// grid 12x12 one wave, double buffered. 2 smem planes.
// ============================================================================
#define KC 304
#define ROWP 40                    // smem row stride in halfs
#define OFF_A 0
#define OFF_B 10240                // 128*40*2
#define BUF_BYTES 21760            // 10240 + 144*40*2
#define SMEM_VAL (2 * BUF_BYTES)   // 43520

struct StageV {
    uint4 a[2], b[3];
};

__device__ __forceinline__ void ldg_chunk(int m0, int n0, int k0, int tid, StageV& s) {
    const uint4 z = make_uint4(0, 0, 0, 0);
    #pragma unroll
    for (int it = 0; it < 2; it++) {
        int i = it * 256 + tid;
        int m = i >> 2, kc = (i & 3) * 8;
        s.a[it] = z;
        if (k0 + kc < BANKN)
            s.a[it] = *(const uint4*)&g_V16[(size_t)(m0 + m) * BANKN + k0 + kc];
    }
    #pragma unroll
    for (int it = 0; it < 3; it++) {
        int i = it * 256 + tid;
        s.b[it] = z;
        if (i < 576) {
            int r = i >> 2, kc = (i & 3) * 8;
            if (n0 + r < NQ && k0 + kc < BANKN)
                s.b[it] = *(const uint4*)&g_P16[(size_t)(n0 + r) * BANKN + k0 + kc];
        }
    }
}

__device__ __forceinline__ void sts_chunk(char* buf, int tid, const StageV& s) {
    #pragma unroll
    for (int it = 0; it < 2; it++) {
        int i = it * 256 + tid;
        int m = i >> 2, kc = (i & 3) * 8;
        *(uint4*)(buf + OFF_A + (m * ROWP + kc) * 2) = s.a[it];
    }
    #pragma unroll
    for (int it = 0; it < 3; it++) {
        int i = it * 256 + tid;
        if (i < 576) {
            int r = i >> 2, kc = (i & 3) * 8;
            *(uint4*)(buf + OFF_B + (r * ROWP + kc) * 2) = s.b[it];
        }
    }
}

__global__ __launch_bounds__(256, 1) void val_gemm_mma(float* __restrict__ out) {
    extern __shared__ char smem[];
    const uint32_t sb = smem_u32(smem);
    const int tid = threadIdx.x;
    const int wid = tid >> 5;
    const int lane = tid & 31;
    const int g = lane >> 2, tg = lane & 3;
    const int wm = wid & 3;
    const int wn = wid >> 2;
    const int n0 = blockIdx.x * 144;
    const int m0 = blockIdx.y * 128;

    const int av_row = (lane & 7) + (((lane >> 3) & 1) << 3);
    const int av_col = (lane >> 4) << 3;
    const int bv_row = (lane & 7) + ((lane >> 4) << 3);
    const int bv_col = ((lane >> 3) & 1) << 3;
    const int b2_row = lane & 7;
    const int b2_col = ((lane >> 3) & 1) << 3;

    float acc[2][9][4] = {};

    {
        StageV s;
        ldg_chunk(m0, n0, 0, tid, s);
        sts_chunk(smem, tid, s);
    }
    __syncthreads();

    for (int c = 0; c < KC; c++) {
        const uint32_t boff = (uint32_t)(c & 1) * BUF_BYTES;
        char* nbuf = smem + (size_t)((c + 1) & 1) * BUF_BYTES;

        StageV s;
        const bool more = (c + 1 < KC);
        if (more) ldg_chunk(m0, n0, (c + 1) * 32, tid, s);

        #pragma unroll
        for (int ks = 0; ks < 2; ks++) {
            const int kk = ks * 16;
            uint32_t a[2][4];
            #pragma unroll
            for (int mt = 0; mt < 2; mt++) {
                uint32_t off = (uint32_t)((wm * 32 + mt * 16 + av_row) * ROWP + kk + av_col) * 2;
                ldsm_x4(a[mt], sb + boff + OFF_A + off);
            }
            #pragma unroll
            for (int p = 0; p < 4; p++) {
                uint32_t off = (uint32_t)((wn * 72 + p * 16 + bv_row) * ROWP + kk + bv_col) * 2;
                uint32_t b[4];
                ldsm_x4(b, sb + boff + OFF_B + off);
                #pragma unroll
                for (int mt = 0; mt < 2; mt++) {
                    mma_f16(acc[mt][2 * p],     a[mt], b);
                    mma_f16(acc[mt][2 * p + 1], a[mt], b + 2);
                }
            }
            {   // leftover nt = 8
                uint32_t off = (uint32_t)((wn * 72 + 64 + b2_row) * ROWP + kk + b2_col) * 2;
                uint32_t b2[2];
                ldsm_x2(b2, sb + boff + OFF_B + off);
                #pragma unroll
                for (int mt = 0; mt < 2; mt++)
                    mma_f16(acc[mt][8], a[mt], b2);
            }
        }

        if (more) sts_chunk(nbuf, tid, s);
        __syncthreads();
    }

    const int n_base = n0 + wn * 72;
    const int m_base = m0 + wm * 32;
    #pragma unroll
    for (int mt = 0; mt < 2; mt++) {
        int rt = m_base + mt * 16 + g;
        int rb = rt + 8;
        float* row_t = out + (size_t)((rt >> 9) * 1024 + (rt & 511)) * NQ;
        float* row_b = out + (size_t)((rb >> 9) * 1024 + (rb & 511)) * NQ;
        #pragma unroll
        for (int nt = 0; nt < 9; nt++) {
            int n = n_base + nt * 8 + tg * 2;
            if (n < NQ) {
                *(float2*)&row_t[n] = make_float2(acc[mt][nt][0], acc[mt][nt][1]);
                *(float2*)&row_b[n] = make_float2(acc[mt][nt][2], acc[mt][nt][3]);
            }
        }
    }
}

// ============================================================================
// Kernel 4: out[o][512+c][n] = q_out[o][c][n] * mask_mem[o][n]
// ============================================================================
__global__ __launch_bounds__(256) void apply_mask(const float* __restrict__ q_out,
                                                  float* __restrict__ out) {
    int idx = blockIdx.x * 256 + threadIdx.x;
    const int total = OBJN * 512 * NQ;
    if (idx >= total) return;
    int n    = idx % NQ;
    int rest = idx / NQ;
    int c    = rest % 512;
    int o    = rest / 512;
    out[(size_t)(o * 1024 + 512 + c) * NQ + n] = q_out[idx] * g_mask[o * NQ + n];
}

// ============================================================================
extern "C" void kernel_launch(void* const* d_in, const int* in_sizes, int n_in,
                              void* d_out, int out_size) {
    const float* keys   = (const float*)d_in[0];  // (128, 9720)
    const float* q_in   = (const float*)d_in[1];  // (1, 128, 1620)
    const float* q_out  = (const float*)d_in[2];  // (3, 512, 1620)
    const float* values = (const float*)d_in[3];  // (3, 512, 9720)
    const float* masks  = (const float*)d_in[4];  // (3, 1, 9720)
    float* out = (float*)d_out;                   // (1, 3, 1024, 1620)

    (void)in_sizes; (void)n_in; (void)out_size;

    cudaFuncSetAttribute(qk_mma, cudaFuncAttributeMaxDynamicSharedMemorySize, SMEM_QK);
    cudaFuncSetAttribute(val_gemm_mma, cudaFuncAttributeMaxDynamicSharedMemorySize, SMEM_VAL);

    dim3 g1((BANKN + 127) / 128, (NQ + 127) / 128);   // 76 x 13
    qk_mma<<<g1, 256, SMEM_QK>>>(keys, q_in);         // launch 0

    softmax_rows<<<NQ, 256>>>(masks);                 // launch 1

    const int convN = (int)(((size_t)M3 * BANKN / 4 + 255) / 256);
    conv_v<<<convN, 256>>>(values);                   // launch 2 (independent)

    dim3 g3(12, 12);                                  // one wave, 144 CTAs
    val_gemm_mma<<<g3, 256, SMEM_VAL>>>(out);         // launch 3 (profiled slot)

    apply_mask<<<(OBJN * 512 * NQ + 255) / 256, 256>>>(q_out, out);  // launch 4
}

// round 17
// speedup vs baseline: 2.3472x; 1.3113x over previous
#include <cuda_runtime.h>
#include <cuda_bf16.h>
#include <cuda_fp16.h>
#include <cstdint>

#define D_KEYC 128
#define BANKN  9720
#define NQ     1620
#define OBJN   3
#define M3     1536

// Scratch (device globals — no allocation allowed)
__device__ float g_P[(size_t)NQ * BANKN];              // fp32 logits
__device__ __half g_P16[(size_t)NQ * BANKN];           // softmax probs, fp16
__device__ __half g_V16[(size_t)M3 * BANKN];           // values, fp16
__device__ float g_mask[OBJN * NQ];                    // mask_mem[o][n]

// ============================================================================
// Common helpers
// ============================================================================
__device__ __forceinline__ uint32_t smem_u32(const void* p) {
    uint32_t a;
    asm("{ .reg .u64 t; cvta.to.shared.u64 t, %1; cvt.u32.u64 %0, t; }"
        : "=r"(a) : "l"(p));
    return a;
}

__device__ __forceinline__ void mma_bf16(float* d, const uint32_t* a, const uint32_t* b) {
    asm volatile(
        "mma.sync.aligned.m16n8k16.row.col.f32.bf16.bf16.f32 "
        "{%0,%1,%2,%3}, {%4,%5,%6,%7}, {%8,%9}, {%0,%1,%2,%3};"
        : "+f"(d[0]), "+f"(d[1]), "+f"(d[2]), "+f"(d[3])
        : "r"(a[0]), "r"(a[1]), "r"(a[2]), "r"(a[3]), "r"(b[0]), "r"(b[1]));
}

__device__ __forceinline__ void mma_f16(float* d, const uint32_t* a, const uint32_t* b) {
    asm volatile(
        "mma.sync.aligned.m16n8k16.row.col.f32.f16.f16.f32 "
        "{%0,%1,%2,%3}, {%4,%5,%6,%7}, {%8,%9}, {%0,%1,%2,%3};"
        : "+f"(d[0]), "+f"(d[1]), "+f"(d[2]), "+f"(d[3])
        : "r"(a[0]), "r"(a[1]), "r"(a[2]), "r"(a[3]), "r"(b[0]), "r"(b[1]));
}

__device__ __forceinline__ void ldsm_x4(uint32_t* r, uint32_t addr) {
    asm volatile("ldmatrix.sync.aligned.m8n8.x4.shared.b16 {%0,%1,%2,%3}, [%4];"
                 : "=r"(r[0]), "=r"(r[1]), "=r"(r[2]), "=r"(r[3]) : "r"(addr));
}
__device__ __forceinline__ void ldsm_x4t(uint32_t* r, uint32_t addr) {
    asm volatile("ldmatrix.sync.aligned.m8n8.x4.trans.shared.b16 {%0,%1,%2,%3}, [%4];"
                 : "=r"(r[0]), "=r"(r[1]), "=r"(r[2]), "=r"(r[3]) : "r"(addr));
}
__device__ __forceinline__ void ldsm_x2(uint32_t* r, uint32_t addr) {
    asm volatile("ldmatrix.sync.aligned.m8n8.x2.shared.b16 {%0,%1}, [%2];"
                 : "=r"(r[0]), "=r"(r[1]) : "r"(addr));
}

// split fp32 -> bf16 hi + bf16 lo (for qk_mma)
__device__ __forceinline__ void split_pack4(float4 v, uint2& h, uint2& l) {
    __nv_bfloat162 hxy = __floats2bfloat162_rn(v.x, v.y);
    __nv_bfloat162 hzw = __floats2bfloat162_rn(v.z, v.w);
    float2 hf0 = __bfloat1622float2(hxy);
    float2 hf1 = __bfloat1622float2(hzw);
    __nv_bfloat162 lxy = __floats2bfloat162_rn(v.x - hf0.x, v.y - hf0.y);
    __nv_bfloat162 lzw = __floats2bfloat162_rn(v.z - hf1.x, v.w - hf1.y);
    h.x = *(uint32_t*)&hxy; h.y = *(uint32_t*)&hzw;
    l.x = *(uint32_t*)&lxy; l.y = *(uint32_t*)&lzw;
}

// ============================================================================
// Kernel 1: S[n][k] = scale * sum_d q[d][n] * keys[d][k]  via bf16 mma x3.
// (unchanged — logits need full accuracy for softmax)
// ============================================================================
#define DROW 136
#define QT_BYTES (128 * DROW * 2)
#define QAHI 0
#define QALO (QT_BYTES)
#define QBHI (2 * QT_BYTES)
#define QBLO (3 * QT_BYTES)
#define SMEM_QK (4 * QT_BYTES)           // 139264

__global__ __launch_bounds__(256, 1) void qk_mma(const float* __restrict__ keys,
                                                 const float* __restrict__ q) {
    extern __shared__ char smem[];
    const uint32_t sb = smem_u32(smem);
    const int tid = threadIdx.x;
    const int lane = tid & 31;
    const int wid = tid >> 5;
    const int g = lane >> 2, tg = lane & 3;
    const int wm = wid & 3;
    const int wn = wid >> 2;
    const int k0 = blockIdx.x * 128;
    const int n0 = blockIdx.y * 128;
    const float scale = 0.08838834764831845f;

    #pragma unroll
    for (int it = 0; it < 16; it++) {
        int i = it * 256 + tid;
        int d = i >> 5, c4 = (i & 31) * 4;
        uint32_t dst = (uint32_t)(d * DROW + c4) * 2;

        float4 v = make_float4(0.f, 0.f, 0.f, 0.f);
        if (n0 + c4 < NQ) {
            v = *(const float4*)&q[(size_t)d * NQ + n0 + c4];
            v.x *= scale; v.y *= scale; v.z *= scale; v.w *= scale;
        }
        uint2 h, l; split_pack4(v, h, l);
        *(uint2*)(smem + QAHI + dst) = h;
        *(uint2*)(smem + QALO + dst) = l;

        float4 w = make_float4(0.f, 0.f, 0.f, 0.f);
        if (k0 + c4 < BANKN)
            w = *(const float4*)&keys[(size_t)d * BANKN + k0 + c4];
        split_pack4(w, h, l);
        *(uint2*)(smem + QBHI + dst) = h;
        *(uint2*)(smem + QBLO + dst) = l;
    }
    __syncthreads();

    float acc[2][8][4] = {};

    const int a_row_l = (lane & 7) + ((lane >> 4) << 3);
    const int a_col_l = ((lane >> 3) & 1) << 3;
    const int b_row_l = (lane & 7) + (((lane >> 3) & 1) << 3);
    const int b_col_l = (lane >> 4) << 3;

    #pragma unroll
    for (int ks = 0; ks < 8; ks++) {
        const int kk = ks * 16;
        uint32_t ah[2][4], al[2][4];
        #pragma unroll
        for (int mt = 0; mt < 2; mt++) {
            uint32_t off = (uint32_t)((kk + a_row_l) * DROW + wm * 32 + mt * 16 + a_col_l) * 2;
            ldsm_x4t(ah[mt], sb + QAHI + off);
            ldsm_x4t(al[mt], sb + QALO + off);
        }
        #pragma unroll
        for (int p = 0; p < 4; p++) {
            uint32_t off = (uint32_t)((kk + b_row_l) * DROW + wn * 64 + p * 16 + b_col_l) * 2;
            uint32_t bh[4], bl[4];
            ldsm_x4t(bh, sb + QBHI + off);
            ldsm_x4t(bl, sb + QBLO + off);
            #pragma unroll
            for (int mt = 0; mt < 2; mt++) {
                mma_bf16(acc[mt][2 * p],     ah[mt], bh);
                mma_bf16(acc[mt][2 * p],     ah[mt], bl);
                mma_bf16(acc[mt][2 * p],     al[mt], bh);
                mma_bf16(acc[mt][2 * p + 1], ah[mt], bh + 2);
                mma_bf16(acc[mt][2 * p + 1], ah[mt], bl + 2);
                mma_bf16(acc[mt][2 * p + 1], al[mt], bh + 2);
            }
        }
    }

    #pragma unroll
    for (int mt = 0; mt < 2; mt++) {
        int nt_ = n0 + wm * 32 + mt * 16 + g;
        int nb_ = nt_ + 8;
        #pragma unroll
        for (int nt = 0; nt < 8; nt++) {
            int k = k0 + wn * 64 + nt * 8 + tg * 2;
            if (k < BANKN) {
                if (nt_ < NQ)
                    *(float2*)&g_P[(size_t)nt_ * BANKN + k] =
                        make_float2(acc[mt][nt][0], acc[mt][nt][1]);
                if (nb_ < NQ)
                    *(float2*)&g_P[(size_t)nb_ * BANKN + k] =
                        make_float2(acc[mt][nt][2], acc[mt][nt][3]);
            }
        }
    }
}

// ============================================================================
// Kernel 2: row softmax of g_P -> single fp16 plane, + fused mask dots.
// ============================================================================
__global__ __launch_bounds__(256) void softmax_rows(const float* __restrict__ masks) {
    __shared__ float4 buf4[BANKN / 4];
    __shared__ float  sred[4][8];

    const int tid = threadIdx.x;
    const size_t rbase = (size_t)blockIdx.x * BANKN;
    const float4* r4 = (const float4*)(g_P + rbase);

    float mx = -3.0e38f;
    for (int i = tid; i < BANKN / 4; i += 256) {
        float4 v = r4[i];
        buf4[i] = v;
        mx = fmaxf(mx, fmaxf(fmaxf(v.x, v.y), fmaxf(v.z, v.w)));
    }
    #pragma unroll
    for (int o = 16; o; o >>= 1) mx = fmaxf(mx, __shfl_xor_sync(0xffffffffu, mx, o));
    if ((tid & 31) == 0) sred[0][tid >> 5] = mx;
    __syncthreads();
    mx = sred[0][0];
    #pragma unroll
    for (int w = 1; w < 8; w++) mx = fmaxf(mx, sred[0][w]);
    __syncthreads();

    float sum = 0.f, m0 = 0.f, m1 = 0.f, m2 = 0.f;
    const float4* mk0 = (const float4*)masks;
    const float4* mk1 = (const float4*)(masks + BANKN);
    const float4* mk2 = (const float4*)(masks + 2 * BANKN);
    for (int i = tid; i < BANKN / 4; i += 256) {
        float4 v = buf4[i];
        v.x = __expf(v.x - mx); v.y = __expf(v.y - mx);
        v.z = __expf(v.z - mx); v.w = __expf(v.w - mx);
        buf4[i] = v;
        sum += (v.x + v.y) + (v.z + v.w);
        float4 a = mk0[i], b = mk1[i], c = mk2[i];
        m0 += a.x * v.x + a.y * v.y + a.z * v.z + a.w * v.w;
        m1 += b.x * v.x + b.y * v.y + b.z * v.z + b.w * v.w;
        m2 += c.x * v.x + c.y * v.y + c.z * v.z + c.w * v.w;
    }
    float vals[4] = {sum, m0, m1, m2};
    #pragma unroll
    for (int r = 0; r < 4; r++) {
        float v = vals[r];
        #pragma unroll
        for (int o = 16; o; o >>= 1) v += __shfl_xor_sync(0xffffffffu, v, o);
        if ((tid & 31) == 0) sred[r][tid >> 5] = v;
    }
    __syncthreads();
    float tot = 0.f;
    #pragma unroll
    for (int w = 0; w < 8; w++) tot += sred[0][w];
    const float inv = 1.f / tot;

    if (tid < 3) {
        float t = 0.f;
        #pragma unroll
        for (int w = 0; w < 8; w++) t += sred[tid + 1][w];
        g_mask[tid * NQ + blockIdx.x] = t * inv;
    }

    for (int i = tid; i < BANKN / 4; i += 256) {
        float4 v = buf4[i];
        __half2 p01 = __floats2half2_rn(v.x * inv, v.y * inv);
        __half2 p23 = __floats2half2_rn(v.z * inv, v.w * inv);
        uint2 u;
        u.x = *(uint32_t*)&p01; u.y = *(uint32_t*)&p23;
        *(uint2*)&g_P16[rbase + (size_t)i * 4] = u;
    }
}

// ============================================================================
// Kernel 2b: convert V to a single fp16 plane (one pass)
// ============================================================================
__global__ __launch_bounds__(256) void conv_v(const float* __restrict__ V) {
    size_t i = (size_t)blockIdx.x * 256 + threadIdx.x;
    const size_t total4 = (size_t)M3 * BANKN / 4;
    if (i >= total4) return;
    float4 v = *(const float4*)&V[i * 4];
    __half2 h01 = __floats2half2_rn(v.x, v.y);
    __half2 h23 = __floats2half2_rn(v.z, v.w);
    uint2 u;
    u.x = *(uint32_t*)&h01; u.y = *(uint32_t*)&h23;
    *(uint2*)&g_V16[i * 4] = u;
}

// ============================================================================
// Kernel 3: mem[r][n] = sum_k V[r][k] * P[n][k], fp16 mma + ldmatrix.
// K-chunk 64 (was 32): halves per-chunk fixed costs (barrier + STS drain +
// LDG exposure) and gives next chunk's LDG a 72-MMA body to hide under.
// 128m x 144n, 8 warps 4m x 2n, grid 12x12 one wave, double buffered.
// ============================================================================
#define KC 152                     // ceil(9720/64)
#define ROWP 72                    // smem row stride in halfs (64 + 8 pad)
#define OFF_A 0
#define OFF_B 18432                // 128*72*2
#define BUF_BYTES 39168            // 18432 + 144*72*2
#define SMEM_VAL (2 * BUF_BYTES)   // 78336

struct StageV {
    uint4 a[4], b[5];
};

__device__ __forceinline__ void ldg_chunk(int m0, int n0, int k0, int tid, StageV& s) {
    const uint4 z = make_uint4(0, 0, 0, 0);
    // A: 128 rows x 64 halfs = 1024 uint4
    #pragma unroll
    for (int it = 0; it < 4; it++) {
        int i = it * 256 + tid;
        int m = i >> 3, kc = (i & 7) * 8;
        s.a[it] = z;
        if (k0 + kc < BANKN)
            s.a[it] = *(const uint4*)&g_V16[(size_t)(m0 + m) * BANKN + k0 + kc];
    }
    // B: 144 rows x 64 halfs = 1152 uint4
    #pragma unroll
    for (int it = 0; it < 5; it++) {
        int i = it * 256 + tid;
        s.b[it] = z;
        if (i < 1152) {
            int r = i >> 3, kc = (i & 7) * 8;
            if (n0 + r < NQ && k0 + kc < BANKN)
                s.b[it] = *(const uint4*)&g_P16[(size_t)(n0 + r) * BANKN + k0 + kc];
        }
    }
}

__device__ __forceinline__ void sts_chunk(char* buf, int tid, const StageV& s) {
    #pragma unroll
    for (int it = 0; it < 4; it++) {
        int i = it * 256 + tid;
        int m = i >> 3, kc = (i & 7) * 8;
        *(uint4*)(buf + OFF_A + (m * ROWP + kc) * 2) = s.a[it];
    }
    #pragma unroll
    for (int it = 0; it < 5; it++) {
        int i = it * 256 + tid;
        if (i < 1152) {
            int r = i >> 3, kc = (i & 7) * 8;
            *(uint4*)(buf + OFF_B + (r * ROWP + kc) * 2) = s.b[it];
        }
    }
}

__global__ __launch_bounds__(256, 1) void val_gemm_mma(float* __restrict__ out) {
    extern __shared__ char smem[];
    const uint32_t sb = smem_u32(smem);
    const int tid = threadIdx.x;
    const int wid = tid >> 5;
    const int lane = tid & 31;
    const int g = lane >> 2, tg = lane & 3;
    const int wm = wid & 3;
    const int wn = wid >> 2;
    const int n0 = blockIdx.x * 144;
    const int m0 = blockIdx.y * 128;

    const int av_row = (lane & 7) + (((lane >> 3) & 1) << 3);
    const int av_col = (lane >> 4) << 3;
    const int bv_row = (lane & 7) + ((lane >> 4) << 3);
    const int bv_col = ((lane >> 3) & 1) << 3;
    const int b2_row = lane & 7;
    const int b2_col = ((lane >> 3) & 1) << 3;

    float acc[2][9][4] = {};

    {
        StageV s;
        ldg_chunk(m0, n0, 0, tid, s);
        sts_chunk(smem, tid, s);
    }
    __syncthreads();

    for (int c = 0; c < KC; c++) {
        const uint32_t boff = (uint32_t)(c & 1) * BUF_BYTES;
        char* nbuf = smem + (size_t)((c + 1) & 1) * BUF_BYTES;

        StageV s;
        const bool more = (c + 1 < KC);
        if (more) ldg_chunk(m0, n0, (c + 1) * 64, tid, s);

        #pragma unroll
        for (int ks = 0; ks < 4; ks++) {
            const int kk = ks * 16;
            uint32_t a[2][4];
            #pragma unroll
            for (int mt = 0; mt < 2; mt++) {
                uint32_t off = (uint32_t)((wm * 32 + mt * 16 + av_row) * ROWP + kk + av_col) * 2;
                ldsm_x4(a[mt], sb + boff + OFF_A + off);
            }
            #pragma unroll
            for (int p = 0; p < 4; p++) {
                uint32_t off = (uint32_t)((wn * 72 + p * 16 + bv_row) * ROWP + kk + bv_col) * 2;
                uint32_t b[4];
                ldsm_x4(b, sb + boff + OFF_B + off);
                #pragma unroll
                for (int mt = 0; mt < 2; mt++) {
                    mma_f16(acc[mt][2 * p],     a[mt], b);
                    mma_f16(acc[mt][2 * p + 1], a[mt], b + 2);
                }
            }
            {   // leftover nt = 8
                uint32_t off = (uint32_t)((wn * 72 + 64 + b2_row) * ROWP + kk + b2_col) * 2;
                uint32_t b2[2];
                ldsm_x2(b2, sb + boff + OFF_B + off);
                #pragma unroll
                for (int mt = 0; mt < 2; mt++)
                    mma_f16(acc[mt][8], a[mt], b2);
            }
        }

        if (more) sts_chunk(nbuf, tid, s);
        __syncthreads();
    }

    const int n_base = n0 + wn * 72;
    const int m_base = m0 + wm * 32;
    #pragma unroll
    for (int mt = 0; mt < 2; mt++) {
        int rt = m_base + mt * 16 + g;
        int rb = rt + 8;
        float* row_t = out + (size_t)((rt >> 9) * 1024 + (rt & 511)) * NQ;
        float* row_b = out + (size_t)((rb >> 9) * 1024 + (rb & 511)) * NQ;
        #pragma unroll
        for (int nt = 0; nt < 9; nt++) {
            int n = n_base + nt * 8 + tg * 2;
            if (n < NQ) {
                *(float2*)&row_t[n] = make_float2(acc[mt][nt][0], acc[mt][nt][1]);
                *(float2*)&row_b[n] = make_float2(acc[mt][nt][2], acc[mt][nt][3]);
            }
        }
    }
}

// ============================================================================
// Kernel 4: out[o][512+c][n] = q_out[o][c][n] * mask_mem[o][n]
// ============================================================================
__global__ __launch_bounds__(256) void apply_mask(const float* __restrict__ q_out,
                                                  float* __restrict__ out) {
    int idx = blockIdx.x * 256 + threadIdx.x;
    const int total = OBJN * 512 * NQ;
    if (idx >= total) return;
    int n    = idx % NQ;
    int rest = idx / NQ;
    int c    = rest % 512;
    int o    = rest / 512;
    out[(size_t)(o * 1024 + 512 + c) * NQ + n] = q_out[idx] * g_mask[o * NQ + n];
}

// ============================================================================
extern "C" void kernel_launch(void* const* d_in, const int* in_sizes, int n_in,
                              void* d_out, int out_size) {
    const float* keys   = (const float*)d_in[0];  // (128, 9720)
    const float* q_in   = (const float*)d_in[1];  // (1, 128, 1620)
    const float* q_out  = (const float*)d_in[2];  // (3, 512, 1620)
    const float* values = (const float*)d_in[3];  // (3, 512, 9720)
    const float* masks  = (const float*)d_in[4];  // (3, 1, 9720)
    float* out = (float*)d_out;                   // (1, 3, 1024, 1620)

    (void)in_sizes; (void)n_in; (void)out_size;

    cudaFuncSetAttribute(qk_mma, cudaFuncAttributeMaxDynamicSharedMemorySize, SMEM_QK);
    cudaFuncSetAttribute(val_gemm_mma, cudaFuncAttributeMaxDynamicSharedMemorySize, SMEM_VAL);

    dim3 g1((BANKN + 127) / 128, (NQ + 127) / 128);   // 76 x 13
    qk_mma<<<g1, 256, SMEM_QK>>>(keys, q_in);         // launch 0

    softmax_rows<<<NQ, 256>>>(masks);                 // launch 1

    const int convN = (int)(((size_t)M3 * BANKN / 4 + 255) / 256);
    conv_v<<<convN, 256>>>(values);                   // launch 2 (independent)

    dim3 g3(12, 12);                                  // one wave, 144 CTAs
    val_gemm_mma<<<g3, 256, SMEM_VAL>>>(out);         // launch 3 (profiled slot)

    apply_mask<<<(OBJN * 512 * NQ + 255) / 256, 256>>>(q_out, out);  // launch 4
}